// round 1
// baseline (speedup 1.0000x reference)
#include <cuda_runtime.h>
#include <cuda_bf16.h>
#include <math_constants.h>

// Problem constants
#define BATCH 2
#define SEQ 2048
#define DIM 4096
#define NH 32
#define NKV 8
#define HD 128
#define TOKENS (BATCH * SEQ)   // 4096

// ---------------------------------------------------------------------------
// Scratch (device globals; no runtime allocation allowed)
// ---------------------------------------------------------------------------
__device__ float g_q[(size_t)TOKENS * (NH * HD)];     // [token, h*128+d]
__device__ float g_k[(size_t)TOKENS * (NKV * HD)];
__device__ float g_v[(size_t)TOKENS * (NKV * HD)];
__device__ float g_attn[(size_t)TOKENS * (NH * HD)];  // attention output

// ---------------------------------------------------------------------------
// SGEMM: C[M,N] = A[M,K] * B[N,K]^T   (A,B,C row-major; M,N mult of 128, K mult of 8)
// 256 threads, 128x128 block tile, 8x8 per-thread micro-tile, BK=8
// ---------------------------------------------------------------------------
__global__ __launch_bounds__(256) void sgemm_abt(
    const float* __restrict__ A, const float* __restrict__ B,
    float* __restrict__ C, int M, int N, int K)
{
    __shared__ float As[8][128];
    __shared__ float Bs[8][128];

    const int tid = threadIdx.x;
    const int tx = tid & 15;       // 0..15 -> N
    const int ty = tid >> 4;       // 0..15 -> M
    const int m0 = blockIdx.y * 128;
    const int n0 = blockIdx.x * 128;

    const int ld_row = tid >> 1;          // 0..127
    const int ld_col = (tid & 1) * 4;     // 0 or 4

    float acc[8][8];
#pragma unroll
    for (int i = 0; i < 8; i++)
#pragma unroll
        for (int j = 0; j < 8; j++) acc[i][j] = 0.f;

    const float* Aptr = A + (size_t)(m0 + ld_row) * K + ld_col;
    const float* Bptr = B + (size_t)(n0 + ld_row) * K + ld_col;

    for (int k0 = 0; k0 < K; k0 += 8) {
        float4 av = *(const float4*)(Aptr + k0);
        float4 bv = *(const float4*)(Bptr + k0);
        As[ld_col + 0][ld_row] = av.x;
        As[ld_col + 1][ld_row] = av.y;
        As[ld_col + 2][ld_row] = av.z;
        As[ld_col + 3][ld_row] = av.w;
        Bs[ld_col + 0][ld_row] = bv.x;
        Bs[ld_col + 1][ld_row] = bv.y;
        Bs[ld_col + 2][ld_row] = bv.z;
        Bs[ld_col + 3][ld_row] = bv.w;
        __syncthreads();

#pragma unroll
        for (int kk = 0; kk < 8; kk++) {
            float4 a0 = *(const float4*)&As[kk][ty * 8];
            float4 a1 = *(const float4*)&As[kk][ty * 8 + 4];
            float4 b0 = *(const float4*)&Bs[kk][tx * 8];
            float4 b1 = *(const float4*)&Bs[kk][tx * 8 + 4];
            float a[8] = {a0.x, a0.y, a0.z, a0.w, a1.x, a1.y, a1.z, a1.w};
            float b[8] = {b0.x, b0.y, b0.z, b0.w, b1.x, b1.y, b1.z, b1.w};
#pragma unroll
            for (int i = 0; i < 8; i++)
#pragma unroll
                for (int j = 0; j < 8; j++)
                    acc[i][j] = fmaf(a[i], b[j], acc[i][j]);
        }
        __syncthreads();
    }

#pragma unroll
    for (int i = 0; i < 8; i++) {
        float* crow = C + (size_t)(m0 + ty * 8 + i) * N + n0 + tx * 8;
        *(float4*)(crow)     = make_float4(acc[i][0], acc[i][1], acc[i][2], acc[i][3]);
        *(float4*)(crow + 4) = make_float4(acc[i][4], acc[i][5], acc[i][6], acc[i][7]);
    }
}

// ---------------------------------------------------------------------------
// RoPE (in place) on x laid out [token, n_heads*128]
// out[d]    = x[d]*cos[s,d]   - x[d+64]*sin[s,d]      (d < 64)
// out[d+64] = x[d+64]*cos[s,d] + x[d]*sin[s,d]        (cos/sin halves equal)
// ---------------------------------------------------------------------------
__global__ void rope_kernel(float* __restrict__ x,
                            const float* __restrict__ cosT,
                            const float* __restrict__ sinT,
                            int n_heads)
{
    int idx = blockIdx.x * blockDim.x + threadIdx.x;
    int total = TOKENS * n_heads * 64;
    if (idx >= total) return;
    int d = idx & 63;
    int h = (idx >> 6) % n_heads;
    int t = idx / (64 * n_heads);
    int s = t & (SEQ - 1);
    float c  = cosT[s * HD + d];
    float sn = sinT[s * HD + d];
    size_t base = (size_t)t * (n_heads * HD) + h * HD + d;
    float x1 = x[base];
    float x2 = x[base + 64];
    x[base]      = x1 * c - x2 * sn;
    x[base + 64] = x2 * c + x1 * sn;
}

// ---------------------------------------------------------------------------
// Flash attention, fp32, causal, GQA (4 q heads per kv head)
// Grid: (SEQ/64, BATCH*NH). 256 threads. Dynamic smem ~115 KB.
//   Qs[128][64] (dim-major), Ks[128][64], Vs[64][128], Ps[64][65]
// Thread (ty,tx) in 16x16: scores micro 4x4, output micro 4(q) x 8(d).
// ---------------------------------------------------------------------------
#define BQ 64
#define BKV 64
#define FLASH_SMEM ((HD*BQ + HD*BKV + BKV*HD + BQ*65) * sizeof(float))

__global__ __launch_bounds__(256) void flash_kernel(
    const float* __restrict__ Q, const float* __restrict__ K,
    const float* __restrict__ V, float* __restrict__ O)
{
    extern __shared__ float sm[];
    float* Qs = sm;                      // [HD][BQ]
    float* Ks = Qs + HD * BQ;            // [HD][BKV]
    float* Vs = Ks + HD * BKV;           // [BKV][HD]
    float* Ps = Vs + (size_t)BKV * HD;   // [BQ][65]

    const int tid = threadIdx.x;
    const int tx = tid & 15;
    const int ty = tid >> 4;
    const int qb = blockIdx.x;               // q tile
    const int bh = blockIdx.y;               // b*NH + h
    const int b = bh / NH;
    const int h = bh % NH;
    const int kh = h / (NH / NKV);
    const int q0 = qb * BQ;
    const float scale = 0.08838834764831845f;  // 1/sqrt(128)

    const size_t q_base  = (size_t)b * SEQ * (NH * HD)  + (size_t)h  * HD;
    const size_t kv_base = (size_t)b * SEQ * (NKV * HD) + (size_t)kh * HD;

    // Load Q tile transposed + pre-scaled: Qs[d][q]
    for (int i = tid; i < BQ * (HD / 4); i += 256) {
        int q  = i >> 5;            // /(HD/4)
        int d4 = (i & 31) << 2;
        float4 v = *(const float4*)&Q[q_base + (size_t)(q0 + q) * (NH * HD) + d4];
        Qs[(d4 + 0) * BQ + q] = v.x * scale;
        Qs[(d4 + 1) * BQ + q] = v.y * scale;
        Qs[(d4 + 2) * BQ + q] = v.z * scale;
        Qs[(d4 + 3) * BQ + q] = v.w * scale;
    }

    float m_i[4], l_i[4], o_reg[4][8];
#pragma unroll
    for (int i = 0; i < 4; i++) {
        m_i[i] = -CUDART_INF_F;
        l_i[i] = 0.f;
#pragma unroll
        for (int j = 0; j < 8; j++) o_reg[i][j] = 0.f;
    }
    __syncthreads();

    const int n_kt = qb + 1;  // causal: aligned tiles up to the diagonal
    for (int kt = 0; kt < n_kt; kt++) {
        const int k0 = kt * BKV;
        // Load K transposed (Ks[d][k]) and V direct (Vs[k][d])
        for (int i = tid; i < BKV * (HD / 4); i += 256) {
            int r  = i >> 5;
            int d4 = (i & 31) << 2;
            const float* src = &K[kv_base + (size_t)(k0 + r) * (NKV * HD) + d4];
            float4 kv = *(const float4*)src;
            Ks[(d4 + 0) * BKV + r] = kv.x;
            Ks[(d4 + 1) * BKV + r] = kv.y;
            Ks[(d4 + 2) * BKV + r] = kv.z;
            Ks[(d4 + 3) * BKV + r] = kv.w;
            float4 vv = *(const float4*)&V[kv_base + (size_t)(k0 + r) * (NKV * HD) + d4];
            *(float4*)&Vs[r * HD + d4] = vv;
        }
        __syncthreads();

        // S = (Q*scale) @ K^T, 4x4 micro-tile
        float s_reg[4][4];
#pragma unroll
        for (int i = 0; i < 4; i++)
#pragma unroll
            for (int j = 0; j < 4; j++) s_reg[i][j] = 0.f;

#pragma unroll 4
        for (int kk = 0; kk < HD; kk++) {
            float4 a = *(const float4*)&Qs[kk * BQ + ty * 4];
            float4 bb = *(const float4*)&Ks[kk * BKV + tx * 4];
            float av[4] = {a.x, a.y, a.z, a.w};
            float bv[4] = {bb.x, bb.y, bb.z, bb.w};
#pragma unroll
            for (int i = 0; i < 4; i++)
#pragma unroll
                for (int j = 0; j < 4; j++)
                    s_reg[i][j] = fmaf(av[i], bv[j], s_reg[i][j]);
        }

        if (kt == qb) {  // diagonal tile: causal mask
#pragma unroll
            for (int i = 0; i < 4; i++)
#pragma unroll
                for (int j = 0; j < 4; j++)
                    if (k0 + tx * 4 + j > q0 + ty * 4 + i) s_reg[i][j] = -1e30f;
        }

        // Online softmax per row (rows owned by ty; 16-lane tx groups)
#pragma unroll
        for (int i = 0; i < 4; i++) {
            float rm = s_reg[i][0];
#pragma unroll
            for (int j = 1; j < 4; j++) rm = fmaxf(rm, s_reg[i][j]);
#pragma unroll
            for (int off = 8; off >= 1; off >>= 1)
                rm = fmaxf(rm, __shfl_xor_sync(0xffffffffu, rm, off));
            float m_new = fmaxf(m_i[i], rm);
            float corr  = __expf(m_i[i] - m_new);
            float rs = 0.f;
#pragma unroll
            for (int j = 0; j < 4; j++) {
                float p = __expf(s_reg[i][j] - m_new);
                s_reg[i][j] = p;
                rs += p;
            }
#pragma unroll
            for (int off = 8; off >= 1; off >>= 1)
                rs += __shfl_xor_sync(0xffffffffu, rs, off);
            l_i[i] = l_i[i] * corr + rs;
            m_i[i] = m_new;
#pragma unroll
            for (int j = 0; j < 8; j++) o_reg[i][j] *= corr;
#pragma unroll
            for (int j = 0; j < 4; j++)
                Ps[(ty * 4 + i) * 65 + tx * 4 + j] = s_reg[i][j];
        }
        __syncthreads();

        // O += P @ V  (output micro: 4 q rows x 8 d cols)
#pragma unroll 4
        for (int k = 0; k < BKV; k++) {
            float p[4];
#pragma unroll
            for (int i = 0; i < 4; i++) p[i] = Ps[(ty * 4 + i) * 65 + k];
            float4 v0 = *(const float4*)&Vs[k * HD + tx * 8];
            float4 v1 = *(const float4*)&Vs[k * HD + tx * 8 + 4];
            float vv[8] = {v0.x, v0.y, v0.z, v0.w, v1.x, v1.y, v1.z, v1.w};
#pragma unroll
            for (int i = 0; i < 4; i++)
#pragma unroll
                for (int j = 0; j < 8; j++)
                    o_reg[i][j] = fmaf(p[i], vv[j], o_reg[i][j]);
        }
        __syncthreads();
    }

    // Normalize and store
#pragma unroll
    for (int i = 0; i < 4; i++) {
        float inv_l = 1.f / l_i[i];
        int q = q0 + ty * 4 + i;
        float* dst = O + (size_t)(b * SEQ + q) * (NH * HD) + h * HD + tx * 8;
        *(float4*)(dst)     = make_float4(o_reg[i][0] * inv_l, o_reg[i][1] * inv_l,
                                          o_reg[i][2] * inv_l, o_reg[i][3] * inv_l);
        *(float4*)(dst + 4) = make_float4(o_reg[i][4] * inv_l, o_reg[i][5] * inv_l,
                                          o_reg[i][6] * inv_l, o_reg[i][7] * inv_l);
    }
}

// ---------------------------------------------------------------------------
// Launcher
// ---------------------------------------------------------------------------
extern "C" void kernel_launch(void* const* d_in, const int* in_sizes, int n_in,
                              void* d_out, int out_size)
{
    const float* data = (const float*)d_in[0];
    const float* Wq   = (const float*)d_in[1];
    const float* Wk   = (const float*)d_in[2];
    const float* Wv   = (const float*)d_in[3];
    const float* Wo   = (const float*)d_in[4];
    const float* cosT = (const float*)d_in[5];
    const float* sinT = (const float*)d_in[6];
    float* out = (float*)d_out;
    (void)in_sizes; (void)n_in; (void)out_size;

    float *q, *k, *v, *attn;
    cudaGetSymbolAddress((void**)&q,    g_q);
    cudaGetSymbolAddress((void**)&k,    g_k);
    cudaGetSymbolAddress((void**)&v,    g_v);
    cudaGetSymbolAddress((void**)&attn, g_attn);

    cudaFuncSetAttribute(flash_kernel,
                         cudaFuncAttributeMaxDynamicSharedMemorySize,
                         (int)FLASH_SMEM);

    // QKV projections
    sgemm_abt<<<dim3((NH * HD) / 128, TOKENS / 128), 256>>>(data, Wq, q, TOKENS, NH * HD, DIM);
    sgemm_abt<<<dim3((NKV * HD) / 128, TOKENS / 128), 256>>>(data, Wk, k, TOKENS, NKV * HD, DIM);
    sgemm_abt<<<dim3((NKV * HD) / 128, TOKENS / 128), 256>>>(data, Wv, v, TOKENS, NKV * HD, DIM);

    // RoPE in place
    {
        int nq = TOKENS * NH * 64;
        rope_kernel<<<(nq + 255) / 256, 256>>>(q, cosT, sinT, NH);
        int nk = TOKENS * NKV * 64;
        rope_kernel<<<(nk + 255) / 256, 256>>>(k, cosT, sinT, NKV);
    }

    // Causal GQA flash attention
    flash_kernel<<<dim3(SEQ / BQ, BATCH * NH), 256, FLASH_SMEM>>>(q, k, v, attn);

    // Output projection
    sgemm_abt<<<dim3(DIM / 128, TOKENS / 128), 256>>>(attn, Wo, out, TOKENS, DIM, DIM);
}

// round 3
// speedup vs baseline: 1.8287x; 1.8287x over previous
#include <cuda_runtime.h>
#include <cuda_bf16.h>
#include <math_constants.h>
#include <cstdint>

// Problem constants
#define BATCH 2
#define SEQ 2048
#define DIM 4096
#define NH 32
#define NKV 8
#define HD 128
#define TOKENS (BATCH * SEQ)   // 4096

// ---------------------------------------------------------------------------
// Scratch (device globals; no runtime allocation allowed)
// ---------------------------------------------------------------------------
__device__ float g_q[(size_t)TOKENS * (NH * HD)];
__device__ float g_k[(size_t)TOKENS * (NKV * HD)];
__device__ float g_v[(size_t)TOKENS * (NKV * HD)];
__device__ float g_attn[(size_t)TOKENS * (NH * HD)];

__device__ __nv_bfloat16 g_data_hi[(size_t)TOKENS * DIM];
__device__ __nv_bfloat16 g_data_lo[(size_t)TOKENS * DIM];
__device__ __nv_bfloat16 g_wq_hi[(size_t)(NH * HD) * DIM];
__device__ __nv_bfloat16 g_wq_lo[(size_t)(NH * HD) * DIM];
__device__ __nv_bfloat16 g_wk_hi[(size_t)(NKV * HD) * DIM];
__device__ __nv_bfloat16 g_wk_lo[(size_t)(NKV * HD) * DIM];
__device__ __nv_bfloat16 g_wv_hi[(size_t)(NKV * HD) * DIM];
__device__ __nv_bfloat16 g_wv_lo[(size_t)(NKV * HD) * DIM];
__device__ __nv_bfloat16 g_wo_hi[(size_t)DIM * (NH * HD)];
__device__ __nv_bfloat16 g_wo_lo[(size_t)DIM * (NH * HD)];
__device__ __nv_bfloat16 g_attn_hi[(size_t)TOKENS * (NH * HD)];
__device__ __nv_bfloat16 g_attn_lo[(size_t)TOKENS * (NH * HD)];

// ---------------------------------------------------------------------------
// PTX helpers (compute_103-legal: ldmatrix / mma.sync / cp.async only)
// ---------------------------------------------------------------------------
__device__ __forceinline__ uint32_t smem_u32(const void* p) {
    uint32_t a;
    asm("{ .reg .u64 t; cvta.to.shared.u64 t, %1; cvt.u32.u64 %0, t; }"
        : "=r"(a) : "l"(p));
    return a;
}
__device__ __forceinline__ void cp16(uint32_t saddr, const void* g) {
    asm volatile("cp.async.cg.shared.global [%0], [%1], 16;" :: "r"(saddr), "l"(g));
}
__device__ __forceinline__ void ldm_x4(uint32_t* r, uint32_t addr) {
    asm volatile("ldmatrix.sync.aligned.m8n8.x4.shared.b16 {%0,%1,%2,%3}, [%4];"
                 : "=r"(r[0]), "=r"(r[1]), "=r"(r[2]), "=r"(r[3]) : "r"(addr));
}
__device__ __forceinline__ void mma16816(float* d, const uint32_t* a,
                                         uint32_t b0, uint32_t b1) {
    asm volatile(
        "mma.sync.aligned.m16n8k16.row.col.f32.bf16.bf16.f32 "
        "{%0,%1,%2,%3}, {%4,%5,%6,%7}, {%8,%9}, {%0,%1,%2,%3};"
        : "+f"(d[0]), "+f"(d[1]), "+f"(d[2]), "+f"(d[3])
        : "r"(a[0]), "r"(a[1]), "r"(a[2]), "r"(a[3]), "r"(b0), "r"(b1));
}

// ---------------------------------------------------------------------------
// HMMA GEMM: C[M=4096, Ng] = A[4096, 4096] * B[Ng, 4096]^T
// A, B fp32 as hi+lo bf16; 3 passes: (Ahi,Bhi),(Ahi,Blo),(Alo,Bhi)
// Tile 128x128, BK=32, 4-stage cp.async, 8 warps (4m x 2n), warp = 32x64
// ---------------------------------------------------------------------------
#define GK 4096
#define BKC 32
#define PASS_CHUNKS (GK / BKC)       // 128
#define NCHUNK (3 * PASS_CHUNKS)     // 384
#define STAGES 4
#define LDA 40                       // BKC + 8 pad (elems); row stride 80 B
#define B_OFF_BYTES (128 * LDA * 2)  // 10240
#define STAGE_BYTES (256 * LDA * 2)  // 20480
#define GEMM_SMEM (STAGES * STAGE_BYTES)  // 81920

__device__ __forceinline__ void load_chunk_mm(
    int c, uint32_t sbase, int tid, int m0, int n0,
    const __nv_bfloat16* __restrict__ Ahi, const __nv_bfloat16* __restrict__ Alo,
    const __nv_bfloat16* __restrict__ Bhi, const __nv_bfloat16* __restrict__ Blo)
{
    const int phase = c >> 7;            // /PASS_CHUNKS
    const int kc = c & (PASS_CHUNKS - 1);
    const __nv_bfloat16* As = (phase < 2) ? Ahi : Alo;
    const __nv_bfloat16* Bs = (phase == 1) ? Blo : Bhi;
    const size_t ke = (size_t)kc * BKC;
    const int r0 = tid >> 2;             // 0..63
    const int seg = (tid & 3) * 8;       // elem offset
#pragma unroll
    for (int it = 0; it < 2; it++) {
        int r = r0 + it * 64;
        cp16(sbase + (uint32_t)(r * LDA + seg) * 2,
             As + (size_t)(m0 + r) * GK + ke + seg);
        cp16(sbase + B_OFF_BYTES + (uint32_t)(r * LDA + seg) * 2,
             Bs + (size_t)(n0 + r) * GK + ke + seg);
    }
    asm volatile("cp.async.commit_group;" ::: "memory");
}

__global__ __launch_bounds__(256, 2) void gemm_mm(
    const __nv_bfloat16* __restrict__ Ahi, const __nv_bfloat16* __restrict__ Alo,
    const __nv_bfloat16* __restrict__ Bhi, const __nv_bfloat16* __restrict__ Blo,
    float* __restrict__ C, int Ng)
{
    extern __shared__ char dsm[];
    const uint32_t base = smem_u32(dsm);
    const int tid = threadIdx.x;
    const int lane = tid & 31;
    const int w = tid >> 5;
    const int wm = (w >> 1) * 32;   // warp m offset in tile
    const int wn = (w & 1) * 64;    // warp n offset in tile
    const int m0 = blockIdx.y * 128;
    const int n0 = blockIdx.x * 128;

    float acc[2][8][4];
#pragma unroll
    for (int f = 0; f < 2; f++)
#pragma unroll
        for (int j = 0; j < 8; j++)
#pragma unroll
            for (int q = 0; q < 4; q++) acc[f][j][q] = 0.f;

    // ldmatrix per-lane intra-tile byte offsets
    const uint32_t a_off = (uint32_t)(((lane & 15)) * LDA + ((lane >> 4) * 8)) * 2;
    const uint32_t b_off = (uint32_t)(((lane & 7) + ((lane >> 4) << 3)) * LDA
                                      + (((lane >> 3) & 1) * 8)) * 2;

    // Prologue: stages 0..2
#pragma unroll
    for (int s = 0; s < STAGES - 1; s++)
        load_chunk_mm(s, base + s * STAGE_BYTES, tid, m0, n0, Ahi, Alo, Bhi, Blo);

    for (int c = 0; c < NCHUNK; c++) {
        asm volatile("cp.async.wait_group %0;" :: "n"(STAGES - 2) : "memory");
        __syncthreads();

        const int ls = c + STAGES - 1;
        if (ls < NCHUNK)
            load_chunk_mm(ls, base + (ls & (STAGES - 1)) * STAGE_BYTES,
                          tid, m0, n0, Ahi, Alo, Bhi, Blo);
        else
            asm volatile("cp.async.commit_group;" ::: "memory");

        const uint32_t sb = base + (c & (STAGES - 1)) * STAGE_BYTES;
        const uint32_t a_base = sb + (uint32_t)(wm * LDA * 2) + a_off;
        const uint32_t b_base = sb + B_OFF_BYTES + (uint32_t)(wn * LDA * 2) + b_off;

#pragma unroll
        for (int ks = 0; ks < 2; ks++) {
            uint32_t a0[4], a1[4];
            ldm_x4(a0, a_base + ks * 32);
            ldm_x4(a1, a_base + ks * 32 + 16 * LDA * 2);
            uint32_t bf[4][4];
#pragma unroll
            for (int g = 0; g < 4; g++)
                ldm_x4(bf[g], b_base + ks * 32 + g * (16 * LDA * 2));
#pragma unroll
            for (int g = 0; g < 4; g++) {
                mma16816(acc[0][2 * g],     a0, bf[g][0], bf[g][1]);
                mma16816(acc[0][2 * g + 1], a0, bf[g][2], bf[g][3]);
                mma16816(acc[1][2 * g],     a1, bf[g][0], bf[g][1]);
                mma16816(acc[1][2 * g + 1], a1, bf[g][2], bf[g][3]);
            }
        }
    }

    // Epilogue: write accumulators to C
    const int gr = lane >> 2;
    const int gc = (lane & 3) * 2;
#pragma unroll
    for (int f = 0; f < 2; f++) {
        const int row = m0 + wm + f * 16 + gr;
#pragma unroll
        for (int j = 0; j < 8; j++) {
            const int col = n0 + wn + j * 8 + gc;
            *(float2*)&C[(size_t)row * Ng + col] =
                make_float2(acc[f][j][0], acc[f][j][1]);
            *(float2*)&C[(size_t)(row + 8) * Ng + col] =
                make_float2(acc[f][j][2], acc[f][j][3]);
        }
    }
}

// ---------------------------------------------------------------------------
// fp32 -> (hi, lo) bf16 split
// ---------------------------------------------------------------------------
__global__ void split_bf16(const float* __restrict__ x,
                           __nv_bfloat16* __restrict__ hi,
                           __nv_bfloat16* __restrict__ lo, int n4)
{
    int i = blockIdx.x * blockDim.x + threadIdx.x;
    if (i >= n4) return;
    float4 v = ((const float4*)x)[i];
    __nv_bfloat16 h0 = __float2bfloat16(v.x);
    __nv_bfloat16 h1 = __float2bfloat16(v.y);
    __nv_bfloat16 h2 = __float2bfloat16(v.z);
    __nv_bfloat16 h3 = __float2bfloat16(v.w);
    __nv_bfloat16 l0 = __float2bfloat16(v.x - __bfloat162float(h0));
    __nv_bfloat16 l1 = __float2bfloat16(v.y - __bfloat162float(h1));
    __nv_bfloat16 l2 = __float2bfloat16(v.z - __bfloat162float(h2));
    __nv_bfloat16 l3 = __float2bfloat16(v.w - __bfloat162float(h3));
    __nv_bfloat162* hp = (__nv_bfloat162*)hi;
    __nv_bfloat162* lp = (__nv_bfloat162*)lo;
    hp[i * 2 + 0] = __nv_bfloat162(h0, h1);
    hp[i * 2 + 1] = __nv_bfloat162(h2, h3);
    lp[i * 2 + 0] = __nv_bfloat162(l0, l1);
    lp[i * 2 + 1] = __nv_bfloat162(l2, l3);
}

// ---------------------------------------------------------------------------
// RoPE (in place)
// ---------------------------------------------------------------------------
__global__ void rope_kernel(float* __restrict__ x,
                            const float* __restrict__ cosT,
                            const float* __restrict__ sinT,
                            int n_heads)
{
    int idx = blockIdx.x * blockDim.x + threadIdx.x;
    int total = TOKENS * n_heads * 64;
    if (idx >= total) return;
    int d = idx & 63;
    int h = (idx >> 6) % n_heads;
    int t = idx / (64 * n_heads);
    int s = t & (SEQ - 1);
    float c  = cosT[s * HD + d];
    float sn = sinT[s * HD + d];
    size_t base = (size_t)t * (n_heads * HD) + h * HD + d;
    float x1 = x[base];
    float x2 = x[base + 64];
    x[base]      = x1 * c - x2 * sn;
    x[base + 64] = x2 * c + x1 * sn;
}

// ---------------------------------------------------------------------------
// Flash attention, fp32, causal, GQA (unchanged; known-good)
// ---------------------------------------------------------------------------
#define BQ 64
#define BKV 64
#define FLASH_SMEM ((HD*BQ + HD*BKV + BKV*HD + BQ*65) * sizeof(float))

__global__ __launch_bounds__(256) void flash_kernel(
    const float* __restrict__ Q, const float* __restrict__ K,
    const float* __restrict__ V, float* __restrict__ O)
{
    extern __shared__ float sm[];
    float* Qs = sm;
    float* Ks = Qs + HD * BQ;
    float* Vs = Ks + HD * BKV;
    float* Ps = Vs + (size_t)BKV * HD;

    const int tid = threadIdx.x;
    const int tx = tid & 15;
    const int ty = tid >> 4;
    const int qb = blockIdx.x;
    const int bh = blockIdx.y;
    const int b = bh / NH;
    const int h = bh % NH;
    const int kh = h / (NH / NKV);
    const int q0 = qb * BQ;
    const float scale = 0.08838834764831845f;

    const size_t q_base  = (size_t)b * SEQ * (NH * HD)  + (size_t)h  * HD;
    const size_t kv_base = (size_t)b * SEQ * (NKV * HD) + (size_t)kh * HD;

    for (int i = tid; i < BQ * (HD / 4); i += 256) {
        int q  = i >> 5;
        int d4 = (i & 31) << 2;
        float4 v = *(const float4*)&Q[q_base + (size_t)(q0 + q) * (NH * HD) + d4];
        Qs[(d4 + 0) * BQ + q] = v.x * scale;
        Qs[(d4 + 1) * BQ + q] = v.y * scale;
        Qs[(d4 + 2) * BQ + q] = v.z * scale;
        Qs[(d4 + 3) * BQ + q] = v.w * scale;
    }

    float m_i[4], l_i[4], o_reg[4][8];
#pragma unroll
    for (int i = 0; i < 4; i++) {
        m_i[i] = -CUDART_INF_F;
        l_i[i] = 0.f;
#pragma unroll
        for (int j = 0; j < 8; j++) o_reg[i][j] = 0.f;
    }
    __syncthreads();

    const int n_kt = qb + 1;
    for (int kt = 0; kt < n_kt; kt++) {
        const int k0 = kt * BKV;
        for (int i = tid; i < BKV * (HD / 4); i += 256) {
            int r  = i >> 5;
            int d4 = (i & 31) << 2;
            float4 kv = *(const float4*)&K[kv_base + (size_t)(k0 + r) * (NKV * HD) + d4];
            Ks[(d4 + 0) * BKV + r] = kv.x;
            Ks[(d4 + 1) * BKV + r] = kv.y;
            Ks[(d4 + 2) * BKV + r] = kv.z;
            Ks[(d4 + 3) * BKV + r] = kv.w;
            float4 vv = *(const float4*)&V[kv_base + (size_t)(k0 + r) * (NKV * HD) + d4];
            *(float4*)&Vs[r * HD + d4] = vv;
        }
        __syncthreads();

        float s_reg[4][4];
#pragma unroll
        for (int i = 0; i < 4; i++)
#pragma unroll
            for (int j = 0; j < 4; j++) s_reg[i][j] = 0.f;

#pragma unroll 4
        for (int kk = 0; kk < HD; kk++) {
            float4 a = *(const float4*)&Qs[kk * BQ + ty * 4];
            float4 bb = *(const float4*)&Ks[kk * BKV + tx * 4];
            float av[4] = {a.x, a.y, a.z, a.w};
            float bv[4] = {bb.x, bb.y, bb.z, bb.w};
#pragma unroll
            for (int i = 0; i < 4; i++)
#pragma unroll
                for (int j = 0; j < 4; j++)
                    s_reg[i][j] = fmaf(av[i], bv[j], s_reg[i][j]);
        }

        if (kt == qb) {
#pragma unroll
            for (int i = 0; i < 4; i++)
#pragma unroll
                for (int j = 0; j < 4; j++)
                    if (k0 + tx * 4 + j > q0 + ty * 4 + i) s_reg[i][j] = -1e30f;
        }

#pragma unroll
        for (int i = 0; i < 4; i++) {
            float rm = s_reg[i][0];
#pragma unroll
            for (int j = 1; j < 4; j++) rm = fmaxf(rm, s_reg[i][j]);
#pragma unroll
            for (int off = 8; off >= 1; off >>= 1)
                rm = fmaxf(rm, __shfl_xor_sync(0xffffffffu, rm, off));
            float m_new = fmaxf(m_i[i], rm);
            float corr  = __expf(m_i[i] - m_new);
            float rs = 0.f;
#pragma unroll
            for (int j = 0; j < 4; j++) {
                float p = __expf(s_reg[i][j] - m_new);
                s_reg[i][j] = p;
                rs += p;
            }
#pragma unroll
            for (int off = 8; off >= 1; off >>= 1)
                rs += __shfl_xor_sync(0xffffffffu, rs, off);
            l_i[i] = l_i[i] * corr + rs;
            m_i[i] = m_new;
#pragma unroll
            for (int j = 0; j < 8; j++) o_reg[i][j] *= corr;
#pragma unroll
            for (int j = 0; j < 4; j++)
                Ps[(ty * 4 + i) * 65 + tx * 4 + j] = s_reg[i][j];
        }
        __syncthreads();

#pragma unroll 4
        for (int k = 0; k < BKV; k++) {
            float p[4];
#pragma unroll
            for (int i = 0; i < 4; i++) p[i] = Ps[(ty * 4 + i) * 65 + k];
            float4 v0 = *(const float4*)&Vs[k * HD + tx * 8];
            float4 v1 = *(const float4*)&Vs[k * HD + tx * 8 + 4];
            float vv[8] = {v0.x, v0.y, v0.z, v0.w, v1.x, v1.y, v1.z, v1.w};
#pragma unroll
            for (int i = 0; i < 4; i++)
#pragma unroll
                for (int j = 0; j < 8; j++)
                    o_reg[i][j] = fmaf(p[i], vv[j], o_reg[i][j]);
        }
        __syncthreads();
    }

#pragma unroll
    for (int i = 0; i < 4; i++) {
        float inv_l = 1.f / l_i[i];
        int q = q0 + ty * 4 + i;
        float* dst = O + (size_t)(b * SEQ + q) * (NH * HD) + h * HD + tx * 8;
        *(float4*)(dst)     = make_float4(o_reg[i][0] * inv_l, o_reg[i][1] * inv_l,
                                          o_reg[i][2] * inv_l, o_reg[i][3] * inv_l);
        *(float4*)(dst + 4) = make_float4(o_reg[i][4] * inv_l, o_reg[i][5] * inv_l,
                                          o_reg[i][6] * inv_l, o_reg[i][7] * inv_l);
    }
}

// ---------------------------------------------------------------------------
// Launcher
// ---------------------------------------------------------------------------
extern "C" void kernel_launch(void* const* d_in, const int* in_sizes, int n_in,
                              void* d_out, int out_size)
{
    const float* data = (const float*)d_in[0];
    const float* Wq   = (const float*)d_in[1];
    const float* Wk   = (const float*)d_in[2];
    const float* Wv   = (const float*)d_in[3];
    const float* Wo   = (const float*)d_in[4];
    const float* cosT = (const float*)d_in[5];
    const float* sinT = (const float*)d_in[6];
    float* out = (float*)d_out;
    (void)in_sizes; (void)n_in; (void)out_size;

    float *q, *k, *v, *attn;
    cudaGetSymbolAddress((void**)&q,    g_q);
    cudaGetSymbolAddress((void**)&k,    g_k);
    cudaGetSymbolAddress((void**)&v,    g_v);
    cudaGetSymbolAddress((void**)&attn, g_attn);

    __nv_bfloat16 *dh, *dl, *qh, *ql, *kh, *kl, *vh, *vl, *oh, *ol, *ah, *al;
    cudaGetSymbolAddress((void**)&dh, g_data_hi);
    cudaGetSymbolAddress((void**)&dl, g_data_lo);
    cudaGetSymbolAddress((void**)&qh, g_wq_hi);
    cudaGetSymbolAddress((void**)&ql, g_wq_lo);
    cudaGetSymbolAddress((void**)&kh, g_wk_hi);
    cudaGetSymbolAddress((void**)&kl, g_wk_lo);
    cudaGetSymbolAddress((void**)&vh, g_wv_hi);
    cudaGetSymbolAddress((void**)&vl, g_wv_lo);
    cudaGetSymbolAddress((void**)&oh, g_wo_hi);
    cudaGetSymbolAddress((void**)&ol, g_wo_lo);
    cudaGetSymbolAddress((void**)&ah, g_attn_hi);
    cudaGetSymbolAddress((void**)&al, g_attn_lo);

    cudaFuncSetAttribute(flash_kernel,
                         cudaFuncAttributeMaxDynamicSharedMemorySize, (int)FLASH_SMEM);
    cudaFuncSetAttribute(gemm_mm,
                         cudaFuncAttributeMaxDynamicSharedMemorySize, GEMM_SMEM);

    // Split inputs to hi/lo bf16
    {
        int n;
        n = TOKENS * DIM / 4;        split_bf16<<<(n + 255) / 256, 256>>>(data, dh, dl, n);
        n = (NH * HD) * DIM / 4;     split_bf16<<<(n + 255) / 256, 256>>>(Wq, qh, ql, n);
        n = (NKV * HD) * DIM / 4;    split_bf16<<<(n + 255) / 256, 256>>>(Wk, kh, kl, n);
        n = (NKV * HD) * DIM / 4;    split_bf16<<<(n + 255) / 256, 256>>>(Wv, vh, vl, n);
        n = DIM * (NH * HD) / 4;     split_bf16<<<(n + 255) / 256, 256>>>(Wo, oh, ol, n);
    }

    // QKV projections on tensor cores (HMMA)
    gemm_mm<<<dim3((NH * HD) / 128, TOKENS / 128), 256, GEMM_SMEM>>>(dh, dl, qh, ql, q, NH * HD);
    gemm_mm<<<dim3((NKV * HD) / 128, TOKENS / 128), 256, GEMM_SMEM>>>(dh, dl, kh, kl, k, NKV * HD);
    gemm_mm<<<dim3((NKV * HD) / 128, TOKENS / 128), 256, GEMM_SMEM>>>(dh, dl, vh, vl, v, NKV * HD);

    // RoPE in place
    {
        int nq = TOKENS * NH * 64;
        rope_kernel<<<(nq + 255) / 256, 256>>>(q, cosT, sinT, NH);
        int nk = TOKENS * NKV * 64;
        rope_kernel<<<(nk + 255) / 256, 256>>>(k, cosT, sinT, NKV);
    }

    // Causal GQA flash attention (fp32)
    flash_kernel<<<dim3(SEQ / BQ, BATCH * NH), 256, FLASH_SMEM>>>(q, k, v, attn);

    // Output projection
    {
        int n = TOKENS * (NH * HD) / 4;
        split_bf16<<<(n + 255) / 256, 256>>>(attn, ah, al, n);
    }
    gemm_mm<<<dim3(DIM / 128, TOKENS / 128), 256, GEMM_SMEM>>>(ah, al, oh, ol, out, DIM);
}

// round 4
// speedup vs baseline: 3.0821x; 1.6854x over previous
#include <cuda_runtime.h>
#include <cuda_bf16.h>
#include <math_constants.h>
#include <cstdint>

// Problem constants
#define BATCH 2
#define SEQ 2048
#define DIM 4096
#define NH 32
#define NKV 8
#define HD 128
#define TOKENS (BATCH * SEQ)   // 4096

// ---------------------------------------------------------------------------
// Scratch (device globals; no runtime allocation allowed)
// ---------------------------------------------------------------------------
__device__ float g_q[(size_t)TOKENS * (NH * HD)];
__device__ float g_k[(size_t)TOKENS * (NKV * HD)];
__device__ float g_v[(size_t)TOKENS * (NKV * HD)];

__device__ __nv_bfloat16 g_data_hi[(size_t)TOKENS * DIM];
__device__ __nv_bfloat16 g_data_lo[(size_t)TOKENS * DIM];
__device__ __nv_bfloat16 g_wq_hi[(size_t)(NH * HD) * DIM];
__device__ __nv_bfloat16 g_wq_lo[(size_t)(NH * HD) * DIM];
__device__ __nv_bfloat16 g_wk_hi[(size_t)(NKV * HD) * DIM];
__device__ __nv_bfloat16 g_wk_lo[(size_t)(NKV * HD) * DIM];
__device__ __nv_bfloat16 g_wv_hi[(size_t)(NKV * HD) * DIM];
__device__ __nv_bfloat16 g_wv_lo[(size_t)(NKV * HD) * DIM];
__device__ __nv_bfloat16 g_wo_hi[(size_t)DIM * (NH * HD)];
__device__ __nv_bfloat16 g_wo_lo[(size_t)DIM * (NH * HD)];
__device__ __nv_bfloat16 g_attn_hi[(size_t)TOKENS * (NH * HD)];
__device__ __nv_bfloat16 g_attn_lo[(size_t)TOKENS * (NH * HD)];

// Post-RoPE split Q/K and split V (bf16 hi/lo)
__device__ __nv_bfloat16 g_qs_hi[(size_t)TOKENS * (NH * HD)];
__device__ __nv_bfloat16 g_qs_lo[(size_t)TOKENS * (NH * HD)];
__device__ __nv_bfloat16 g_ks_hi[(size_t)TOKENS * (NKV * HD)];
__device__ __nv_bfloat16 g_ks_lo[(size_t)TOKENS * (NKV * HD)];
__device__ __nv_bfloat16 g_vs_hi[(size_t)TOKENS * (NKV * HD)];
__device__ __nv_bfloat16 g_vs_lo[(size_t)TOKENS * (NKV * HD)];

// ---------------------------------------------------------------------------
// PTX helpers (compute_103-legal: ldmatrix / mma.sync / cp.async only)
// ---------------------------------------------------------------------------
__device__ __forceinline__ uint32_t smem_u32(const void* p) {
    uint32_t a;
    asm("{ .reg .u64 t; cvta.to.shared.u64 t, %1; cvt.u32.u64 %0, t; }"
        : "=r"(a) : "l"(p));
    return a;
}
__device__ __forceinline__ void cp16(uint32_t saddr, const void* g) {
    asm volatile("cp.async.cg.shared.global [%0], [%1], 16;" :: "r"(saddr), "l"(g));
}
__device__ __forceinline__ void ldm_x4(uint32_t* r, uint32_t addr) {
    asm volatile("ldmatrix.sync.aligned.m8n8.x4.shared.b16 {%0,%1,%2,%3}, [%4];"
                 : "=r"(r[0]), "=r"(r[1]), "=r"(r[2]), "=r"(r[3]) : "r"(addr));
}
__device__ __forceinline__ void ldm_x4t(uint32_t* r, uint32_t addr) {
    asm volatile("ldmatrix.sync.aligned.m8n8.x4.trans.shared.b16 {%0,%1,%2,%3}, [%4];"
                 : "=r"(r[0]), "=r"(r[1]), "=r"(r[2]), "=r"(r[3]) : "r"(addr));
}
__device__ __forceinline__ void mma16816(float* d, const uint32_t* a,
                                         uint32_t b0, uint32_t b1) {
    asm volatile(
        "mma.sync.aligned.m16n8k16.row.col.f32.bf16.bf16.f32 "
        "{%0,%1,%2,%3}, {%4,%5,%6,%7}, {%8,%9}, {%0,%1,%2,%3};"
        : "+f"(d[0]), "+f"(d[1]), "+f"(d[2]), "+f"(d[3])
        : "r"(a[0]), "r"(a[1]), "r"(a[2]), "r"(a[3]), "r"(b0), "r"(b1));
}
// split (a,b) floats into packed bf16x2 hi and lo (a in low half)
__device__ __forceinline__ void split2(float a, float b, uint32_t& hi, uint32_t& lo) {
    __nv_bfloat16 ha = __float2bfloat16(a), hb = __float2bfloat16(b);
    __nv_bfloat162 H(ha, hb);
    __nv_bfloat162 L(__float2bfloat16(a - __bfloat162float(ha)),
                     __float2bfloat16(b - __bfloat162float(hb)));
    hi = *reinterpret_cast<uint32_t*>(&H);
    lo = *reinterpret_cast<uint32_t*>(&L);
}

// ---------------------------------------------------------------------------
// HMMA GEMM (unchanged from round 3, validated)
// ---------------------------------------------------------------------------
#define GK 4096
#define BKC 32
#define PASS_CHUNKS (GK / BKC)
#define NCHUNK (3 * PASS_CHUNKS)
#define STAGES 4
#define LDA 40
#define B_OFF_BYTES (128 * LDA * 2)
#define STAGE_BYTES (256 * LDA * 2)
#define GEMM_SMEM (STAGES * STAGE_BYTES)

__device__ __forceinline__ void load_chunk_mm(
    int c, uint32_t sbase, int tid, int m0, int n0,
    const __nv_bfloat16* __restrict__ Ahi, const __nv_bfloat16* __restrict__ Alo,
    const __nv_bfloat16* __restrict__ Bhi, const __nv_bfloat16* __restrict__ Blo)
{
    const int phase = c >> 7;
    const int kc = c & (PASS_CHUNKS - 1);
    const __nv_bfloat16* As = (phase < 2) ? Ahi : Alo;
    const __nv_bfloat16* Bs = (phase == 1) ? Blo : Bhi;
    const size_t ke = (size_t)kc * BKC;
    const int r0 = tid >> 2;
    const int seg = (tid & 3) * 8;
#pragma unroll
    for (int it = 0; it < 2; it++) {
        int r = r0 + it * 64;
        cp16(sbase + (uint32_t)(r * LDA + seg) * 2,
             As + (size_t)(m0 + r) * GK + ke + seg);
        cp16(sbase + B_OFF_BYTES + (uint32_t)(r * LDA + seg) * 2,
             Bs + (size_t)(n0 + r) * GK + ke + seg);
    }
    asm volatile("cp.async.commit_group;" ::: "memory");
}

__global__ __launch_bounds__(256, 2) void gemm_mm(
    const __nv_bfloat16* __restrict__ Ahi, const __nv_bfloat16* __restrict__ Alo,
    const __nv_bfloat16* __restrict__ Bhi, const __nv_bfloat16* __restrict__ Blo,
    float* __restrict__ C, int Ng)
{
    extern __shared__ char dsm[];
    const uint32_t base = smem_u32(dsm);
    const int tid = threadIdx.x;
    const int lane = tid & 31;
    const int w = tid >> 5;
    const int wm = (w >> 1) * 32;
    const int wn = (w & 1) * 64;
    const int m0 = blockIdx.y * 128;
    const int n0 = blockIdx.x * 128;

    float acc[2][8][4];
#pragma unroll
    for (int f = 0; f < 2; f++)
#pragma unroll
        for (int j = 0; j < 8; j++)
#pragma unroll
            for (int q = 0; q < 4; q++) acc[f][j][q] = 0.f;

    const uint32_t a_off = (uint32_t)(((lane & 15)) * LDA + ((lane >> 4) * 8)) * 2;
    const uint32_t b_off = (uint32_t)(((lane & 7) + ((lane >> 4) << 3)) * LDA
                                      + (((lane >> 3) & 1) * 8)) * 2;

#pragma unroll
    for (int s = 0; s < STAGES - 1; s++)
        load_chunk_mm(s, base + s * STAGE_BYTES, tid, m0, n0, Ahi, Alo, Bhi, Blo);

    for (int c = 0; c < NCHUNK; c++) {
        asm volatile("cp.async.wait_group %0;" :: "n"(STAGES - 2) : "memory");
        __syncthreads();

        const int ls = c + STAGES - 1;
        if (ls < NCHUNK)
            load_chunk_mm(ls, base + (ls & (STAGES - 1)) * STAGE_BYTES,
                          tid, m0, n0, Ahi, Alo, Bhi, Blo);
        else
            asm volatile("cp.async.commit_group;" ::: "memory");

        const uint32_t sb = base + (c & (STAGES - 1)) * STAGE_BYTES;
        const uint32_t a_base = sb + (uint32_t)(wm * LDA * 2) + a_off;
        const uint32_t b_base = sb + B_OFF_BYTES + (uint32_t)(wn * LDA * 2) + b_off;

#pragma unroll
        for (int ks = 0; ks < 2; ks++) {
            uint32_t a0[4], a1[4];
            ldm_x4(a0, a_base + ks * 32);
            ldm_x4(a1, a_base + ks * 32 + 16 * LDA * 2);
            uint32_t bf[4][4];
#pragma unroll
            for (int g = 0; g < 4; g++)
                ldm_x4(bf[g], b_base + ks * 32 + g * (16 * LDA * 2));
#pragma unroll
            for (int g = 0; g < 4; g++) {
                mma16816(acc[0][2 * g],     a0, bf[g][0], bf[g][1]);
                mma16816(acc[0][2 * g + 1], a0, bf[g][2], bf[g][3]);
                mma16816(acc[1][2 * g],     a1, bf[g][0], bf[g][1]);
                mma16816(acc[1][2 * g + 1], a1, bf[g][2], bf[g][3]);
            }
        }
    }

    const int gr = lane >> 2;
    const int gc = (lane & 3) * 2;
#pragma unroll
    for (int f = 0; f < 2; f++) {
        const int row = m0 + wm + f * 16 + gr;
#pragma unroll
        for (int j = 0; j < 8; j++) {
            const int col = n0 + wn + j * 8 + gc;
            *(float2*)&C[(size_t)row * Ng + col] =
                make_float2(acc[f][j][0], acc[f][j][1]);
            *(float2*)&C[(size_t)(row + 8) * Ng + col] =
                make_float2(acc[f][j][2], acc[f][j][3]);
        }
    }
}

// ---------------------------------------------------------------------------
// fp32 -> (hi, lo) bf16 split
// ---------------------------------------------------------------------------
__global__ void split_bf16(const float* __restrict__ x,
                           __nv_bfloat16* __restrict__ hi,
                           __nv_bfloat16* __restrict__ lo, int n4)
{
    int i = blockIdx.x * blockDim.x + threadIdx.x;
    if (i >= n4) return;
    float4 v = ((const float4*)x)[i];
    __nv_bfloat16 h0 = __float2bfloat16(v.x);
    __nv_bfloat16 h1 = __float2bfloat16(v.y);
    __nv_bfloat16 h2 = __float2bfloat16(v.z);
    __nv_bfloat16 h3 = __float2bfloat16(v.w);
    __nv_bfloat16 l0 = __float2bfloat16(v.x - __bfloat162float(h0));
    __nv_bfloat16 l1 = __float2bfloat16(v.y - __bfloat162float(h1));
    __nv_bfloat16 l2 = __float2bfloat16(v.z - __bfloat162float(h2));
    __nv_bfloat16 l3 = __float2bfloat16(v.w - __bfloat162float(h3));
    __nv_bfloat162* hp = (__nv_bfloat162*)hi;
    __nv_bfloat162* lp = (__nv_bfloat162*)lo;
    hp[i * 2 + 0] = __nv_bfloat162(h0, h1);
    hp[i * 2 + 1] = __nv_bfloat162(h2, h3);
    lp[i * 2 + 0] = __nv_bfloat162(l0, l1);
    lp[i * 2 + 1] = __nv_bfloat162(l2, l3);
}

// ---------------------------------------------------------------------------
// RoPE + optional softmax scale + hi/lo split (reads fp32, writes bf16 hi/lo)
// ---------------------------------------------------------------------------
__global__ void rope_split(const float* __restrict__ x,
                           __nv_bfloat16* __restrict__ hi,
                           __nv_bfloat16* __restrict__ lo,
                           const float* __restrict__ cosT,
                           const float* __restrict__ sinT,
                           int n_heads, float scale)
{
    int idx = blockIdx.x * blockDim.x + threadIdx.x;
    int total = TOKENS * n_heads * 64;
    if (idx >= total) return;
    int d = idx & 63;
    int h = (idx >> 6) % n_heads;
    int t = idx / (64 * n_heads);
    int s = t & (SEQ - 1);
    float c  = cosT[s * HD + d];
    float sn = sinT[s * HD + d];
    size_t base = (size_t)t * (n_heads * HD) + h * HD + d;
    float x1 = x[base], x2 = x[base + 64];
    float y1 = (x1 * c - x2 * sn) * scale;
    float y2 = (x2 * c + x1 * sn) * scale;
    __nv_bfloat16 h1 = __float2bfloat16(y1);
    __nv_bfloat16 h2 = __float2bfloat16(y2);
    hi[base]      = h1;
    hi[base + 64] = h2;
    lo[base]      = __float2bfloat16(y1 - __bfloat162float(h1));
    lo[base + 64] = __float2bfloat16(y2 - __bfloat162float(h2));
}

// ---------------------------------------------------------------------------
// Flash attention on HMMA, causal, GQA, 3-term bf16 split everywhere.
// BQ=128, BKV=64. 8 warps: warp w owns q rows [w*16, w*16+16).
// K/V hi/lo double-buffered via cp.async; Q frags persistent in registers.
// Writes output directly as bf16 hi/lo for the O-projection GEMM.
// ---------------------------------------------------------------------------
#define LDV 136                  // padded row (elems); 272 B
#define LDVB (LDV * 2)
#define FBUF (64 * LDVB)         // one 64-row buffer: 17408 B
#define FSTG (4 * FBUF)          // stage = Khi,Klo,Vhi,Vlo: 69632 B
#define FLASH2_SMEM (2 * FSTG)   // 139264 B

__device__ __forceinline__ void load_kv(uint32_t sb, int tid,
    const __nv_bfloat16* __restrict__ khi, const __nv_bfloat16* __restrict__ klo,
    const __nv_bfloat16* __restrict__ vhi, const __nv_bfloat16* __restrict__ vlo,
    size_t kvbase)
{
#pragma unroll
    for (int i = 0; i < 4; i++) {
        int idx = tid + i * 256;
        int r = idx >> 4, sg = idx & 15;
        size_t g = kvbase + (size_t)r * (NKV * HD) + sg * 8;
        uint32_t s = sb + r * LDVB + sg * 16;
        cp16(s,            khi + g);
        cp16(s + FBUF,     klo + g);
        cp16(s + 2 * FBUF, vhi + g);
        cp16(s + 3 * FBUF, vlo + g);
    }
    asm volatile("cp.async.commit_group;" ::: "memory");
}

__global__ __launch_bounds__(256) void flash_mma(
    const __nv_bfloat16* __restrict__ qhi, const __nv_bfloat16* __restrict__ qlo,
    const __nv_bfloat16* __restrict__ khi, const __nv_bfloat16* __restrict__ klo,
    const __nv_bfloat16* __restrict__ vhi, const __nv_bfloat16* __restrict__ vlo,
    __nv_bfloat16* __restrict__ ohi, __nv_bfloat16* __restrict__ olo)
{
    extern __shared__ char dsm[];
    const uint32_t base = smem_u32(dsm);
    const int tid = threadIdx.x;
    const int lane = tid & 31;
    const int w = tid >> 5;
    const int qb = gridDim.x - 1 - blockIdx.x;   // heavy tiles first
    const int bh = blockIdx.y;
    const int b = bh / NH, h = bh % NH;
    const int kh = h / (NH / NKV);
    const int q0 = qb * 128;

    const size_t qbase = ((size_t)b * SEQ + q0) * (NH * HD) + (size_t)h * HD;
    const size_t kvh   = ((size_t)b * SEQ) * (NKV * HD) + (size_t)kh * HD;

    // Stage Q (128 rows hi+lo) through stage-0 smem, extract frags to regs
#pragma unroll
    for (int i = 0; i < 8; i++) {
        int idx = tid + i * 256;
        int r = idx >> 4, sg = idx & 15;
        size_t g = qbase + (size_t)r * (NH * HD) + sg * 8;
        cp16(base + r * LDVB + sg * 16,            qhi + g);
        cp16(base + 2 * FBUF + r * LDVB + sg * 16, qlo + g);
    }
    asm volatile("cp.async.commit_group;" ::: "memory");
    asm volatile("cp.async.wait_group 0;" ::: "memory");
    __syncthreads();

    uint32_t qa_h[8][4], qa_l[8][4];
    {
        const uint32_t qrow = base + (w * 16 + (lane & 15)) * LDVB + (lane >> 4) * 16;
#pragma unroll
        for (int ks = 0; ks < 8; ks++) {
            ldm_x4(qa_h[ks], qrow + ks * 32);
            ldm_x4(qa_l[ks], qrow + 2 * FBUF + ks * 32);
        }
    }
    __syncthreads();

    float o[16][4];
#pragma unroll
    for (int j = 0; j < 16; j++)
#pragma unroll
        for (int q = 0; q < 4; q++) o[j][q] = 0.f;
    float m0 = -CUDART_INF_F, m1 = -CUDART_INF_F, l0 = 0.f, l1 = 0.f;

    const int n = 2 * (qb + 1);
    load_kv(base, tid, khi, klo, vhi, vlo, kvh);   // tile 0 -> stage 0

    const uint32_t koff = ((lane & 7) + ((lane >> 4) << 3)) * LDVB + ((lane >> 3) & 1) * 16;
    const uint32_t voff = (lane & 15) * LDVB + (lane >> 4) * 16;

    for (int t = 0; t < n; t++) {
        asm volatile("cp.async.wait_group 0;" ::: "memory");
        __syncthreads();
        if (t + 1 < n)
            load_kv(base + ((t + 1) & 1) * FSTG, tid, khi, klo, vhi, vlo,
                    kvh + (size_t)(t + 1) * 64 * (NKV * HD));

        const uint32_t sb = base + (t & 1) * FSTG;

        // S = Q K^T (3 split terms)
        float s[8][4];
#pragma unroll
        for (int f = 0; f < 8; f++)
#pragma unroll
            for (int q = 0; q < 4; q++) s[f][q] = 0.f;

#pragma unroll
        for (int ks = 0; ks < 8; ks++) {
#pragma unroll
            for (int g = 0; g < 4; g++) {
                uint32_t kbh[4], kbl[4];
                ldm_x4(kbh, sb + g * 16 * LDVB + ks * 32 + koff);
                ldm_x4(kbl, sb + FBUF + g * 16 * LDVB + ks * 32 + koff);
                mma16816(s[2 * g],     qa_h[ks], kbh[0], kbh[1]);
                mma16816(s[2 * g + 1], qa_h[ks], kbh[2], kbh[3]);
                mma16816(s[2 * g],     qa_h[ks], kbl[0], kbl[1]);
                mma16816(s[2 * g + 1], qa_h[ks], kbl[2], kbl[3]);
                mma16816(s[2 * g],     qa_l[ks], kbh[0], kbh[1]);
                mma16816(s[2 * g + 1], qa_l[ks], kbh[2], kbh[3]);
            }
        }

        // Causal mask (only last two kv tiles touch the diagonal)
        if (t >= n - 2) {
            const int rA = q0 + w * 16 + (lane >> 2);
            const int cb = t * 64 + 2 * (lane & 3);
#pragma unroll
            for (int f = 0; f < 8; f++) {
                int c = cb + f * 8;
                if (c > rA)         s[f][0] = -1e30f;
                if (c + 1 > rA)     s[f][1] = -1e30f;
                if (c > rA + 8)     s[f][2] = -1e30f;
                if (c + 1 > rA + 8) s[f][3] = -1e30f;
            }
        }

        // Online softmax (rows gr and gr+8)
        float mn0 = m0, mn1 = m1;
#pragma unroll
        for (int f = 0; f < 8; f++) {
            mn0 = fmaxf(mn0, fmaxf(s[f][0], s[f][1]));
            mn1 = fmaxf(mn1, fmaxf(s[f][2], s[f][3]));
        }
        mn0 = fmaxf(mn0, __shfl_xor_sync(0xffffffffu, mn0, 1));
        mn0 = fmaxf(mn0, __shfl_xor_sync(0xffffffffu, mn0, 2));
        mn1 = fmaxf(mn1, __shfl_xor_sync(0xffffffffu, mn1, 1));
        mn1 = fmaxf(mn1, __shfl_xor_sync(0xffffffffu, mn1, 2));
        const float cr0 = __expf(m0 - mn0), cr1 = __expf(m1 - mn1);
        m0 = mn0; m1 = mn1;

        float rs0 = 0.f, rs1 = 0.f;
        uint32_t ph01[8], ph23[8], pl01[8], pl23[8];
#pragma unroll
        for (int f = 0; f < 8; f++) {
            float p0 = __expf(s[f][0] - mn0);
            float p1 = __expf(s[f][1] - mn0);
            float p2 = __expf(s[f][2] - mn1);
            float p3 = __expf(s[f][3] - mn1);
            rs0 += p0 + p1;
            rs1 += p2 + p3;
            split2(p0, p1, ph01[f], pl01[f]);
            split2(p2, p3, ph23[f], pl23[f]);
        }
        rs0 += __shfl_xor_sync(0xffffffffu, rs0, 1);
        rs0 += __shfl_xor_sync(0xffffffffu, rs0, 2);
        rs1 += __shfl_xor_sync(0xffffffffu, rs1, 1);
        rs1 += __shfl_xor_sync(0xffffffffu, rs1, 2);
        l0 = l0 * cr0 + rs0;
        l1 = l1 * cr1 + rs1;
#pragma unroll
        for (int j = 0; j < 16; j++) {
            o[j][0] *= cr0; o[j][1] *= cr0;
            o[j][2] *= cr1; o[j][3] *= cr1;
        }

        // O += P V (3 split terms); V as B via ldmatrix.trans
        const uint32_t vbh = sb + 2 * FBUF + voff;
#pragma unroll
        for (int kc = 0; kc < 4; kc++) {
            uint32_t ah[4] = {ph01[2 * kc], ph23[2 * kc], ph01[2 * kc + 1], ph23[2 * kc + 1]};
            uint32_t al[4] = {pl01[2 * kc], pl23[2 * kc], pl01[2 * kc + 1], pl23[2 * kc + 1]};
#pragma unroll
            for (int g = 0; g < 8; g++) {
                uint32_t vh4[4], vl4[4];
                ldm_x4t(vh4, vbh + kc * 16 * LDVB + g * 32);
                ldm_x4t(vl4, vbh + FBUF + kc * 16 * LDVB + g * 32);
                mma16816(o[2 * g],     ah, vh4[0], vh4[1]);
                mma16816(o[2 * g + 1], ah, vh4[2], vh4[3]);
                mma16816(o[2 * g],     ah, vl4[0], vl4[1]);
                mma16816(o[2 * g + 1], ah, vl4[2], vl4[3]);
                mma16816(o[2 * g],     al, vh4[0], vh4[1]);
                mma16816(o[2 * g + 1], al, vh4[2], vh4[3]);
            }
        }
    }

    // Normalize + write as bf16 hi/lo (feeds O-projection GEMM directly)
    const float il0 = 1.f / l0, il1 = 1.f / l1;
    const int rA = q0 + w * 16 + (lane >> 2);
    const size_t oA = ((size_t)b * SEQ + rA) * (NH * HD) + (size_t)h * HD + 2 * (lane & 3);
    const size_t oB = oA + (size_t)8 * (NH * HD);
#pragma unroll
    for (int j = 0; j < 16; j++) {
        uint32_t h01, lo01, h23, lo23;
        split2(o[j][0] * il0, o[j][1] * il0, h01, lo01);
        split2(o[j][2] * il1, o[j][3] * il1, h23, lo23);
        *(uint32_t*)&ohi[oA + j * 8] = h01;
        *(uint32_t*)&olo[oA + j * 8] = lo01;
        *(uint32_t*)&ohi[oB + j * 8] = h23;
        *(uint32_t*)&olo[oB + j * 8] = lo23;
    }
}

// ---------------------------------------------------------------------------
// Launcher
// ---------------------------------------------------------------------------
extern "C" void kernel_launch(void* const* d_in, const int* in_sizes, int n_in,
                              void* d_out, int out_size)
{
    const float* data = (const float*)d_in[0];
    const float* Wq   = (const float*)d_in[1];
    const float* Wk   = (const float*)d_in[2];
    const float* Wv   = (const float*)d_in[3];
    const float* Wo   = (const float*)d_in[4];
    const float* cosT = (const float*)d_in[5];
    const float* sinT = (const float*)d_in[6];
    float* out = (float*)d_out;
    (void)in_sizes; (void)n_in; (void)out_size;

    float *q, *k, *v;
    cudaGetSymbolAddress((void**)&q, g_q);
    cudaGetSymbolAddress((void**)&k, g_k);
    cudaGetSymbolAddress((void**)&v, g_v);

    __nv_bfloat16 *dh, *dl, *wqh, *wql, *wkh, *wkl, *wvh, *wvl, *woh, *wol, *ah, *al;
    __nv_bfloat16 *qsh, *qsl, *ksh, *ksl, *vsh, *vsl;
    cudaGetSymbolAddress((void**)&dh,  g_data_hi);
    cudaGetSymbolAddress((void**)&dl,  g_data_lo);
    cudaGetSymbolAddress((void**)&wqh, g_wq_hi);
    cudaGetSymbolAddress((void**)&wql, g_wq_lo);
    cudaGetSymbolAddress((void**)&wkh, g_wk_hi);
    cudaGetSymbolAddress((void**)&wkl, g_wk_lo);
    cudaGetSymbolAddress((void**)&wvh, g_wv_hi);
    cudaGetSymbolAddress((void**)&wvl, g_wv_lo);
    cudaGetSymbolAddress((void**)&woh, g_wo_hi);
    cudaGetSymbolAddress((void**)&wol, g_wo_lo);
    cudaGetSymbolAddress((void**)&ah,  g_attn_hi);
    cudaGetSymbolAddress((void**)&al,  g_attn_lo);
    cudaGetSymbolAddress((void**)&qsh, g_qs_hi);
    cudaGetSymbolAddress((void**)&qsl, g_qs_lo);
    cudaGetSymbolAddress((void**)&ksh, g_ks_hi);
    cudaGetSymbolAddress((void**)&ksl, g_ks_lo);
    cudaGetSymbolAddress((void**)&vsh, g_vs_hi);
    cudaGetSymbolAddress((void**)&vsl, g_vs_lo);

    cudaFuncSetAttribute(gemm_mm,
                         cudaFuncAttributeMaxDynamicSharedMemorySize, GEMM_SMEM);
    cudaFuncSetAttribute(flash_mma,
                         cudaFuncAttributeMaxDynamicSharedMemorySize, FLASH2_SMEM);

    // Split inputs to hi/lo bf16
    {
        int n;
        n = TOKENS * DIM / 4;        split_bf16<<<(n + 255) / 256, 256>>>(data, dh, dl, n);
        n = (NH * HD) * DIM / 4;     split_bf16<<<(n + 255) / 256, 256>>>(Wq, wqh, wql, n);
        n = (NKV * HD) * DIM / 4;    split_bf16<<<(n + 255) / 256, 256>>>(Wk, wkh, wkl, n);
        n = (NKV * HD) * DIM / 4;    split_bf16<<<(n + 255) / 256, 256>>>(Wv, wvh, wvl, n);
        n = DIM * (NH * HD) / 4;     split_bf16<<<(n + 255) / 256, 256>>>(Wo, woh, wol, n);
    }

    // QKV projections (HMMA)
    gemm_mm<<<dim3((NH * HD) / 128, TOKENS / 128), 256, GEMM_SMEM>>>(dh, dl, wqh, wql, q, NH * HD);
    gemm_mm<<<dim3((NKV * HD) / 128, TOKENS / 128), 256, GEMM_SMEM>>>(dh, dl, wkh, wkl, k, NKV * HD);
    gemm_mm<<<dim3((NKV * HD) / 128, TOKENS / 128), 256, GEMM_SMEM>>>(dh, dl, wvh, wvl, v, NKV * HD);

    // RoPE + split (softmax scale folded into Q); V plain split
    {
        const float scale = 0.08838834764831845f;   // 1/sqrt(128)
        int nq = TOKENS * NH * 64;
        rope_split<<<(nq + 255) / 256, 256>>>(q, qsh, qsl, cosT, sinT, NH, scale);
        int nk = TOKENS * NKV * 64;
        rope_split<<<(nk + 255) / 256, 256>>>(k, ksh, ksl, cosT, sinT, NKV, 1.0f);
        int nv = TOKENS * (NKV * HD) / 4;
        split_bf16<<<(nv + 255) / 256, 256>>>(v, vsh, vsl, nv);
    }

    // Causal GQA flash attention on HMMA (writes bf16 hi/lo)
    flash_mma<<<dim3(SEQ / 128, BATCH * NH), 256, FLASH2_SMEM>>>(
        qsh, qsl, ksh, ksl, vsh, vsl, ah, al);

    // Output projection (HMMA)
    gemm_mm<<<dim3(DIM / 128, TOKENS / 128), 256, GEMM_SMEM>>>(ah, al, woh, wol, out, DIM);
}

// round 8
// speedup vs baseline: 3.1745x; 1.0300x over previous
#include <cuda_runtime.h>
#include <cuda_bf16.h>
#include <math_constants.h>
#include <cstdint>

// Problem constants
#define BATCH 2
#define SEQ 2048
#define DIM 4096
#define NH 32
#define NKV 8
#define HD 128
#define TOKENS (BATCH * SEQ)   // 4096

// ---------------------------------------------------------------------------
// Scratch (device globals; no runtime allocation allowed)
// ---------------------------------------------------------------------------
__device__ float g_q[(size_t)TOKENS * (NH * HD)];
__device__ float g_k[(size_t)TOKENS * (NKV * HD)];
__device__ float g_v[(size_t)TOKENS * (NKV * HD)];

__device__ __nv_bfloat16 g_data_hi[(size_t)TOKENS * DIM];
__device__ __nv_bfloat16 g_data_lo[(size_t)TOKENS * DIM];
__device__ __nv_bfloat16 g_wq_hi[(size_t)(NH * HD) * DIM];
__device__ __nv_bfloat16 g_wq_lo[(size_t)(NH * HD) * DIM];
__device__ __nv_bfloat16 g_wk_hi[(size_t)(NKV * HD) * DIM];
__device__ __nv_bfloat16 g_wk_lo[(size_t)(NKV * HD) * DIM];
__device__ __nv_bfloat16 g_wv_hi[(size_t)(NKV * HD) * DIM];
__device__ __nv_bfloat16 g_wv_lo[(size_t)(NKV * HD) * DIM];
__device__ __nv_bfloat16 g_wo_hi[(size_t)DIM * (NH * HD)];
__device__ __nv_bfloat16 g_wo_lo[(size_t)DIM * (NH * HD)];
__device__ __nv_bfloat16 g_attn_hi[(size_t)TOKENS * (NH * HD)];
__device__ __nv_bfloat16 g_attn_lo[(size_t)TOKENS * (NH * HD)];

// Post-RoPE split Q/K and split V (bf16 hi/lo)
__device__ __nv_bfloat16 g_qs_hi[(size_t)TOKENS * (NH * HD)];
__device__ __nv_bfloat16 g_qs_lo[(size_t)TOKENS * (NH * HD)];
__device__ __nv_bfloat16 g_ks_hi[(size_t)TOKENS * (NKV * HD)];
__device__ __nv_bfloat16 g_ks_lo[(size_t)TOKENS * (NKV * HD)];
__device__ __nv_bfloat16 g_vs_hi[(size_t)TOKENS * (NKV * HD)];
__device__ __nv_bfloat16 g_vs_lo[(size_t)TOKENS * (NKV * HD)];

// ---------------------------------------------------------------------------
// PTX helpers (compute_103-legal: ldmatrix / mma.sync / cp.async only)
// ---------------------------------------------------------------------------
__device__ __forceinline__ uint32_t smem_u32(const void* p) {
    uint32_t a;
    asm("{ .reg .u64 t; cvta.to.shared.u64 t, %1; cvt.u32.u64 %0, t; }"
        : "=r"(a) : "l"(p));
    return a;
}
__device__ __forceinline__ void cp16(uint32_t saddr, const void* g) {
    asm volatile("cp.async.cg.shared.global [%0], [%1], 16;" :: "r"(saddr), "l"(g));
}
__device__ __forceinline__ void ldm_x4(uint32_t* r, uint32_t addr) {
    asm volatile("ldmatrix.sync.aligned.m8n8.x4.shared.b16 {%0,%1,%2,%3}, [%4];"
                 : "=r"(r[0]), "=r"(r[1]), "=r"(r[2]), "=r"(r[3]) : "r"(addr));
}
__device__ __forceinline__ void ldm_x4t(uint32_t* r, uint32_t addr) {
    asm volatile("ldmatrix.sync.aligned.m8n8.x4.trans.shared.b16 {%0,%1,%2,%3}, [%4];"
                 : "=r"(r[0]), "=r"(r[1]), "=r"(r[2]), "=r"(r[3]) : "r"(addr));
}
__device__ __forceinline__ void mma16816(float* d, const uint32_t* a,
                                         uint32_t b0, uint32_t b1) {
    asm volatile(
        "mma.sync.aligned.m16n8k16.row.col.f32.bf16.bf16.f32 "
        "{%0,%1,%2,%3}, {%4,%5,%6,%7}, {%8,%9}, {%0,%1,%2,%3};"
        : "+f"(d[0]), "+f"(d[1]), "+f"(d[2]), "+f"(d[3])
        : "r"(a[0]), "r"(a[1]), "r"(a[2]), "r"(a[3]), "r"(b0), "r"(b1));
}
__device__ __forceinline__ float ex2(float x) {
    float r;
    asm("ex2.approx.f32 %0, %1;" : "=f"(r) : "f"(x));
    return r;
}
// RN-based split (used in cold paths)
__device__ __forceinline__ void split2(float a, float b, uint32_t& hi, uint32_t& lo) {
    __nv_bfloat16 ha = __float2bfloat16(a), hb = __float2bfloat16(b);
    __nv_bfloat162 H(ha, hb);
    __nv_bfloat162 L(__float2bfloat16(a - __bfloat162float(ha)),
                     __float2bfloat16(b - __bfloat162float(hb)));
    hi = *reinterpret_cast<uint32_t*>(&H);
    lo = *reinterpret_cast<uint32_t*>(&L);
}
// Truncation-based split: hi = top 16 bits (exact bf16), lo = rn(residual). Cheap.
__device__ __forceinline__ void tsplit2(float a, float b, uint32_t& hi, uint32_t& lo) {
    uint32_t ua = __float_as_uint(a), ub = __float_as_uint(b);
    asm("prmt.b32 %0, %1, %2, 0x7632;" : "=r"(hi) : "r"(ua), "r"(ub));
    float ra = a - __uint_as_float(ua & 0xFFFF0000u);
    float rb = b - __uint_as_float(ub & 0xFFFF0000u);
    asm("cvt.rn.bf16x2.f32 %0, %1, %2;" : "=r"(lo) : "f"(rb), "f"(ra));
}

// ---------------------------------------------------------------------------
// HMMA GEMM core (tile 128x128, BK=32, 4-stage cp.async, 8 warps 4m x 2n)
// C[M, Ng] = A[M, 4096] * B[Ng, 4096]^T, A/B fp32 as hi+lo bf16, 3 passes
// ---------------------------------------------------------------------------
#define GK 4096
#define BKC 32
#define PASS_CHUNKS (GK / BKC)
#define NCHUNK (3 * PASS_CHUNKS)
#define STAGES 4
#define LDA 40
#define B_OFF_BYTES (128 * LDA * 2)
#define STAGE_BYTES (256 * LDA * 2)
#define GEMM_SMEM (STAGES * STAGE_BYTES)

__device__ __forceinline__ void load_chunk_mm(
    int c, uint32_t sbase, int tid, int m0, int n0,
    const __nv_bfloat16* __restrict__ Ahi, const __nv_bfloat16* __restrict__ Alo,
    const __nv_bfloat16* __restrict__ Bhi, const __nv_bfloat16* __restrict__ Blo)
{
    const int phase = c >> 7;
    const int kc = c & (PASS_CHUNKS - 1);
    const __nv_bfloat16* As = (phase < 2) ? Ahi : Alo;
    const __nv_bfloat16* Bs = (phase == 1) ? Blo : Bhi;
    const size_t ke = (size_t)kc * BKC;
    const int r0 = tid >> 2;
    const int seg = (tid & 3) * 8;
#pragma unroll
    for (int it = 0; it < 2; it++) {
        int r = r0 + it * 64;
        cp16(sbase + (uint32_t)(r * LDA + seg) * 2,
             As + (size_t)(m0 + r) * GK + ke + seg);
        cp16(sbase + B_OFF_BYTES + (uint32_t)(r * LDA + seg) * 2,
             Bs + (size_t)(n0 + r) * GK + ke + seg);
    }
    asm volatile("cp.async.commit_group;" ::: "memory");
}

__device__ __forceinline__ void gemm_core(
    const __nv_bfloat16* __restrict__ Ahi, const __nv_bfloat16* __restrict__ Alo,
    const __nv_bfloat16* __restrict__ Bhi, const __nv_bfloat16* __restrict__ Blo,
    float* __restrict__ C, int Ng, int m0, int n0, char* dsm)
{
    const uint32_t base = smem_u32(dsm);
    const int tid = threadIdx.x;
    const int lane = tid & 31;
    const int w = tid >> 5;
    const int wm = (w >> 1) * 32;
    const int wn = (w & 1) * 64;

    float acc[2][8][4];
#pragma unroll
    for (int f = 0; f < 2; f++)
#pragma unroll
        for (int j = 0; j < 8; j++)
#pragma unroll
            for (int q = 0; q < 4; q++) acc[f][j][q] = 0.f;

    const uint32_t a_off = (uint32_t)(((lane & 15)) * LDA + ((lane >> 4) * 8)) * 2;
    const uint32_t b_off = (uint32_t)(((lane & 7) + ((lane >> 4) << 3)) * LDA
                                      + (((lane >> 3) & 1) * 8)) * 2;

#pragma unroll
    for (int s = 0; s < STAGES - 1; s++)
        load_chunk_mm(s, base + s * STAGE_BYTES, tid, m0, n0, Ahi, Alo, Bhi, Blo);

    for (int c = 0; c < NCHUNK; c++) {
        asm volatile("cp.async.wait_group %0;" :: "n"(STAGES - 2) : "memory");
        __syncthreads();

        const int ls = c + STAGES - 1;
        if (ls < NCHUNK)
            load_chunk_mm(ls, base + (ls & (STAGES - 1)) * STAGE_BYTES,
                          tid, m0, n0, Ahi, Alo, Bhi, Blo);
        else
            asm volatile("cp.async.commit_group;" ::: "memory");

        const uint32_t sb = base + (c & (STAGES - 1)) * STAGE_BYTES;
        const uint32_t a_base = sb + (uint32_t)(wm * LDA * 2) + a_off;
        const uint32_t b_base = sb + B_OFF_BYTES + (uint32_t)(wn * LDA * 2) + b_off;

#pragma unroll
        for (int ks = 0; ks < 2; ks++) {
            uint32_t a0[4], a1[4];
            ldm_x4(a0, a_base + ks * 32);
            ldm_x4(a1, a_base + ks * 32 + 16 * LDA * 2);
            uint32_t bf[4][4];
#pragma unroll
            for (int g = 0; g < 4; g++)
                ldm_x4(bf[g], b_base + ks * 32 + g * (16 * LDA * 2));
#pragma unroll
            for (int g = 0; g < 4; g++) {
                mma16816(acc[0][2 * g],     a0, bf[g][0], bf[g][1]);
                mma16816(acc[0][2 * g + 1], a0, bf[g][2], bf[g][3]);
                mma16816(acc[1][2 * g],     a1, bf[g][0], bf[g][1]);
                mma16816(acc[1][2 * g + 1], a1, bf[g][2], bf[g][3]);
            }
        }
    }

    const int gr = lane >> 2;
    const int gc = (lane & 3) * 2;
#pragma unroll
    for (int f = 0; f < 2; f++) {
        const int row = m0 + wm + f * 16 + gr;
#pragma unroll
        for (int j = 0; j < 8; j++) {
            const int col = n0 + wn + j * 8 + gc;
            *(float2*)&C[(size_t)row * Ng + col] =
                make_float2(acc[f][j][0], acc[f][j][1]);
            *(float2*)&C[(size_t)(row + 8) * Ng + col] =
                make_float2(acc[f][j][2], acc[f][j][3]);
        }
    }
}

// Fused QKV projection: blockIdx.x 0..31 -> Q, 32..39 -> K, 40..47 -> V
// (K and V each have NKV*HD = 1024 cols = 8 tiles of 128)
__global__ __launch_bounds__(256, 2) void gemm_qkv(
    const __nv_bfloat16* __restrict__ dh, const __nv_bfloat16* __restrict__ dl,
    const __nv_bfloat16* __restrict__ wqh, const __nv_bfloat16* __restrict__ wql,
    const __nv_bfloat16* __restrict__ wkh, const __nv_bfloat16* __restrict__ wkl,
    const __nv_bfloat16* __restrict__ wvh, const __nv_bfloat16* __restrict__ wvl,
    float* __restrict__ q, float* __restrict__ k, float* __restrict__ v)
{
    extern __shared__ char dsm[];
    const int bx = blockIdx.x;
    const __nv_bfloat16 *Bh, *Bl;
    float* C;
    int Ng, n0;
    if (bx < 32)      { Bh = wqh; Bl = wql; C = q; Ng = NH * HD;  n0 = bx * 128; }
    else if (bx < 40) { Bh = wkh; Bl = wkl; C = k; Ng = NKV * HD; n0 = (bx - 32) * 128; }
    else              { Bh = wvh; Bl = wvl; C = v; Ng = NKV * HD; n0 = (bx - 40) * 128; }
    gemm_core(dh, dl, Bh, Bl, C, Ng, blockIdx.y * 128, n0, dsm);
}

// O projection
__global__ __launch_bounds__(256, 2) void gemm_mm(
    const __nv_bfloat16* __restrict__ Ahi, const __nv_bfloat16* __restrict__ Alo,
    const __nv_bfloat16* __restrict__ Bhi, const __nv_bfloat16* __restrict__ Blo,
    float* __restrict__ C, int Ng)
{
    extern __shared__ char dsm[];
    gemm_core(Ahi, Alo, Bhi, Blo, C, Ng, blockIdx.y * 128, blockIdx.x * 128, dsm);
}

// ---------------------------------------------------------------------------
// One fused split kernel for all 5 fp32 inputs (data, Wq, Wk, Wv, Wo)
// Segment sizes in float4 units. (FIX: Wk/Wv are 1024*4096/4 = 1048576, not 524288)
// ---------------------------------------------------------------------------
#define SPLIT_N_DATA  4194304                    // 4096*4096/4
#define SPLIT_N_WQ    4194304                    // 4096*4096/4
#define SPLIT_N_WK    1048576                    // 1024*4096/4
#define SPLIT_N_WV    1048576                    // 1024*4096/4
#define SPLIT_N_WO    4194304                    // 4096*4096/4
#define SPLIT_TOTAL   (SPLIT_N_DATA + SPLIT_N_WQ + SPLIT_N_WK + SPLIT_N_WV + SPLIT_N_WO)

__global__ void split_all(
    const float* __restrict__ data, const float* __restrict__ Wq,
    const float* __restrict__ Wk, const float* __restrict__ Wv,
    const float* __restrict__ Wo,
    __nv_bfloat16* __restrict__ dh, __nv_bfloat16* __restrict__ dl,
    __nv_bfloat16* __restrict__ qh, __nv_bfloat16* __restrict__ ql,
    __nv_bfloat16* __restrict__ kh, __nv_bfloat16* __restrict__ kl,
    __nv_bfloat16* __restrict__ vh, __nv_bfloat16* __restrict__ vl,
    __nv_bfloat16* __restrict__ oh, __nv_bfloat16* __restrict__ ol)
{
    int i = blockIdx.x * 256 + threadIdx.x;
    if (i >= SPLIT_TOTAL) return;
    const float* src; __nv_bfloat16 *hi, *lo; int off;
    if (i < SPLIT_N_DATA) { src = data; hi = dh; lo = dl; off = 0; }
    else if (i < SPLIT_N_DATA + SPLIT_N_WQ)
        { src = Wq; hi = qh; lo = ql; off = SPLIT_N_DATA; }
    else if (i < SPLIT_N_DATA + SPLIT_N_WQ + SPLIT_N_WK)
        { src = Wk; hi = kh; lo = kl; off = SPLIT_N_DATA + SPLIT_N_WQ; }
    else if (i < SPLIT_N_DATA + SPLIT_N_WQ + SPLIT_N_WK + SPLIT_N_WV)
        { src = Wv; hi = vh; lo = vl; off = SPLIT_N_DATA + SPLIT_N_WQ + SPLIT_N_WK; }
    else
        { src = Wo; hi = oh; lo = ol; off = SPLIT_N_DATA + SPLIT_N_WQ + SPLIT_N_WK + SPLIT_N_WV; }
    int j = i - off;
    float4 val = ((const float4*)src)[j];
    uint32_t h01, l01, h23, l23;
    split2(val.x, val.y, h01, l01);
    split2(val.z, val.w, h23, l23);
    ((uint32_t*)hi)[j * 2]     = h01;
    ((uint32_t*)hi)[j * 2 + 1] = h23;
    ((uint32_t*)lo)[j * 2]     = l01;
    ((uint32_t*)lo)[j * 2 + 1] = l23;
}

// ---------------------------------------------------------------------------
// fp32 -> (hi, lo) split (used for V post-projection)
// ---------------------------------------------------------------------------
__global__ void split_bf16(const float* __restrict__ x,
                           __nv_bfloat16* __restrict__ hi,
                           __nv_bfloat16* __restrict__ lo, int n4)
{
    int i = blockIdx.x * blockDim.x + threadIdx.x;
    if (i >= n4) return;
    float4 v = ((const float4*)x)[i];
    uint32_t h01, l01, h23, l23;
    split2(v.x, v.y, h01, l01);
    split2(v.z, v.w, h23, l23);
    ((uint32_t*)hi)[i * 2]     = h01;
    ((uint32_t*)hi)[i * 2 + 1] = h23;
    ((uint32_t*)lo)[i * 2]     = l01;
    ((uint32_t*)lo)[i * 2 + 1] = l23;
}

// ---------------------------------------------------------------------------
// RoPE + scale + hi/lo split
// ---------------------------------------------------------------------------
__global__ void rope_split(const float* __restrict__ x,
                           __nv_bfloat16* __restrict__ hi,
                           __nv_bfloat16* __restrict__ lo,
                           const float* __restrict__ cosT,
                           const float* __restrict__ sinT,
                           int n_heads, float scale)
{
    int idx = blockIdx.x * blockDim.x + threadIdx.x;
    int total = TOKENS * n_heads * 64;
    if (idx >= total) return;
    int d = idx & 63;
    int h = (idx >> 6) % n_heads;
    int t = idx / (64 * n_heads);
    int s = t & (SEQ - 1);
    float c  = cosT[s * HD + d];
    float sn = sinT[s * HD + d];
    size_t base = (size_t)t * (n_heads * HD) + h * HD + d;
    float x1 = x[base], x2 = x[base + 64];
    float y1 = (x1 * c - x2 * sn) * scale;
    float y2 = (x2 * c + x1 * sn) * scale;
    __nv_bfloat16 h1 = __float2bfloat16(y1);
    __nv_bfloat16 h2 = __float2bfloat16(y2);
    hi[base]      = h1;
    hi[base + 64] = h2;
    lo[base]      = __float2bfloat16(y1 - __bfloat162float(h1));
    lo[base + 64] = __float2bfloat16(y2 - __bfloat162float(h2));
}

// ---------------------------------------------------------------------------
// Flash attention on HMMA: two-half softmax pipeline per 64-kv tile.
// BQ=128, 8 warps x 16 q-rows. exp in log2 domain (scale pre-folded into Q).
// ---------------------------------------------------------------------------
#define LDV 136
#define LDVB (LDV * 2)
#define FBUF (64 * LDVB)
#define FSTG (4 * FBUF)
#define FLASH2_SMEM (2 * FSTG)

__device__ __forceinline__ void load_kv(uint32_t sb, int tid,
    const __nv_bfloat16* __restrict__ khi, const __nv_bfloat16* __restrict__ klo,
    const __nv_bfloat16* __restrict__ vhi, const __nv_bfloat16* __restrict__ vlo,
    size_t kvbase)
{
#pragma unroll
    for (int i = 0; i < 4; i++) {
        int idx = tid + i * 256;
        int r = idx >> 4, sg = idx & 15;
        size_t g = kvbase + (size_t)r * (NKV * HD) + sg * 8;
        uint32_t s = sb + r * LDVB + sg * 16;
        cp16(s,            khi + g);
        cp16(s + FBUF,     klo + g);
        cp16(s + 2 * FBUF, vhi + g);
        cp16(s + 3 * FBUF, vlo + g);
    }
    asm volatile("cp.async.commit_group;" ::: "memory");
}

__global__ __launch_bounds__(256) void flash_mma(
    const __nv_bfloat16* __restrict__ qhi, const __nv_bfloat16* __restrict__ qlo,
    const __nv_bfloat16* __restrict__ khi, const __nv_bfloat16* __restrict__ klo,
    const __nv_bfloat16* __restrict__ vhi, const __nv_bfloat16* __restrict__ vlo,
    __nv_bfloat16* __restrict__ ohi, __nv_bfloat16* __restrict__ olo)
{
    extern __shared__ char dsm[];
    const uint32_t base = smem_u32(dsm);
    const int tid = threadIdx.x;
    const int lane = tid & 31;
    const int w = tid >> 5;
    const int qb = gridDim.x - 1 - blockIdx.x;   // heavy tiles first
    const int bh = blockIdx.y;
    const int b = bh / NH, h = bh % NH;
    const int kh = h / (NH / NKV);
    const int q0 = qb * 128;

    const size_t qbase = ((size_t)b * SEQ + q0) * (NH * HD) + (size_t)h * HD;
    const size_t kvh   = ((size_t)b * SEQ) * (NKV * HD) + (size_t)kh * HD;

    // Stage Q through stage-0 smem, extract frags to regs
#pragma unroll
    for (int i = 0; i < 8; i++) {
        int idx = tid + i * 256;
        int r = idx >> 4, sg = idx & 15;
        size_t g = qbase + (size_t)r * (NH * HD) + sg * 8;
        cp16(base + r * LDVB + sg * 16,            qhi + g);
        cp16(base + 2 * FBUF + r * LDVB + sg * 16, qlo + g);
    }
    asm volatile("cp.async.commit_group;" ::: "memory");
    asm volatile("cp.async.wait_group 0;" ::: "memory");
    __syncthreads();

    uint32_t qa_h[8][4], qa_l[8][4];
    {
        const uint32_t qrow = base + (w * 16 + (lane & 15)) * LDVB + (lane >> 4) * 16;
#pragma unroll
        for (int ks = 0; ks < 8; ks++) {
            ldm_x4(qa_h[ks], qrow + ks * 32);
            ldm_x4(qa_l[ks], qrow + 2 * FBUF + ks * 32);
        }
    }
    __syncthreads();

    float o[16][4];
#pragma unroll
    for (int j = 0; j < 16; j++)
#pragma unroll
        for (int q = 0; q < 4; q++) o[j][q] = 0.f;
    float m0 = -CUDART_INF_F, m1 = -CUDART_INF_F, l0 = 0.f, l1 = 0.f;

    const int n = 2 * (qb + 1);
    load_kv(base, tid, khi, klo, vhi, vlo, kvh);   // tile 0 -> stage 0

    const uint32_t koff = ((lane & 7) + ((lane >> 4) << 3)) * LDVB + ((lane >> 3) & 1) * 16;
    const uint32_t voff = (lane & 15) * LDVB + (lane >> 4) * 16;

    for (int t = 0; t < n; t++) {
        asm volatile("cp.async.wait_group 0;" ::: "memory");
        __syncthreads();
        if (t + 1 < n)
            load_kv(base + ((t + 1) & 1) * FSTG, tid, khi, klo, vhi, vlo,
                    kvh + (size_t)(t + 1) * 64 * (NKV * HD));

        const uint32_t sb = base + (t & 1) * FSTG;
        const uint32_t vbh = sb + 2 * FBUF + voff;

        // S = Q K^T, half 0 (g=0,1) then half 1 (g=2,3)
        float s[8][4];
#pragma unroll
        for (int f = 0; f < 8; f++)
#pragma unroll
            for (int q = 0; q < 4; q++) s[f][q] = 0.f;

#pragma unroll
        for (int g = 0; g < 4; g++) {
#pragma unroll
            for (int ks = 0; ks < 8; ks++) {
                uint32_t kbh[4], kbl[4];
                ldm_x4(kbh, sb + g * 16 * LDVB + ks * 32 + koff);
                ldm_x4(kbl, sb + FBUF + g * 16 * LDVB + ks * 32 + koff);
                mma16816(s[2 * g],     qa_h[ks], kbh[0], kbh[1]);
                mma16816(s[2 * g + 1], qa_h[ks], kbh[2], kbh[3]);
                mma16816(s[2 * g],     qa_h[ks], kbl[0], kbl[1]);
                mma16816(s[2 * g + 1], qa_h[ks], kbl[2], kbl[3]);
                mma16816(s[2 * g],     qa_l[ks], kbh[0], kbh[1]);
                mma16816(s[2 * g + 1], qa_l[ks], kbh[2], kbh[3]);
            }
        }

        const bool diag = (t >= n - 2);
        const int rA = q0 + w * 16 + (lane >> 2);
        const int cb = t * 64 + 2 * (lane & 3);

        // Two chained softmax halves; tensor pipe stays busy with S(h1)/PV(h0)
#pragma unroll
        for (int hf = 0; hf < 2; hf++) {
            if (diag) {
#pragma unroll
                for (int j = 0; j < 4; j++) {
                    int f = 4 * hf + j;
                    int c = cb + f * 8;
                    if (c > rA)         s[f][0] = -1e30f;
                    if (c + 1 > rA)     s[f][1] = -1e30f;
                    if (c > rA + 8)     s[f][2] = -1e30f;
                    if (c + 1 > rA + 8) s[f][3] = -1e30f;
                }
            }
            float mn0 = m0, mn1 = m1;
#pragma unroll
            for (int j = 0; j < 4; j++) {
                int f = 4 * hf + j;
                mn0 = fmaxf(mn0, fmaxf(s[f][0], s[f][1]));
                mn1 = fmaxf(mn1, fmaxf(s[f][2], s[f][3]));
            }
            mn0 = fmaxf(mn0, __shfl_xor_sync(0xffffffffu, mn0, 1));
            mn0 = fmaxf(mn0, __shfl_xor_sync(0xffffffffu, mn0, 2));
            mn1 = fmaxf(mn1, __shfl_xor_sync(0xffffffffu, mn1, 1));
            mn1 = fmaxf(mn1, __shfl_xor_sync(0xffffffffu, mn1, 2));
            const float cr0 = ex2(m0 - mn0), cr1 = ex2(m1 - mn1);
            m0 = mn0; m1 = mn1;

            float rs0 = 0.f, rs1 = 0.f;
            uint32_t ph01[4], ph23[4], pl01[4], pl23[4];
#pragma unroll
            for (int j = 0; j < 4; j++) {
                int f = 4 * hf + j;
                float p0 = ex2(s[f][0] - m0);
                float p1 = ex2(s[f][1] - m0);
                float p2 = ex2(s[f][2] - m1);
                float p3 = ex2(s[f][3] - m1);
                rs0 += p0 + p1;
                rs1 += p2 + p3;
                tsplit2(p0, p1, ph01[j], pl01[j]);
                tsplit2(p2, p3, ph23[j], pl23[j]);
            }
            l0 = l0 * cr0 + rs0;   // per-lane partial; reduced after the loop
            l1 = l1 * cr1 + rs1;
#pragma unroll
            for (int j = 0; j < 16; j++) {
                o[j][0] *= cr0; o[j][1] *= cr0;
                o[j][2] *= cr1; o[j][3] *= cr1;
            }
            // PV for this half: kv rows [hf*32, hf*32+32)
#pragma unroll
            for (int kc2 = 0; kc2 < 2; kc2++) {
                const int kc = 2 * hf + kc2;
                uint32_t ah[4] = {ph01[2 * kc2], ph23[2 * kc2],
                                  ph01[2 * kc2 + 1], ph23[2 * kc2 + 1]};
                uint32_t al[4] = {pl01[2 * kc2], pl23[2 * kc2],
                                  pl01[2 * kc2 + 1], pl23[2 * kc2 + 1]};
#pragma unroll
                for (int g = 0; g < 8; g++) {
                    uint32_t vh4[4], vl4[4];
                    ldm_x4t(vh4, vbh + kc * 16 * LDVB + g * 32);
                    ldm_x4t(vl4, vbh + FBUF + kc * 16 * LDVB + g * 32);
                    mma16816(o[2 * g],     ah, vh4[0], vh4[1]);
                    mma16816(o[2 * g + 1], ah, vh4[2], vh4[3]);
                    mma16816(o[2 * g],     ah, vl4[0], vl4[1]);
                    mma16816(o[2 * g + 1], ah, vl4[2], vl4[3]);
                    mma16816(o[2 * g],     al, vh4[0], vh4[1]);
                    mma16816(o[2 * g + 1], al, vh4[2], vh4[3]);
                }
            }
        }
    }

    // Deferred cross-lane l reduction
    l0 += __shfl_xor_sync(0xffffffffu, l0, 1);
    l0 += __shfl_xor_sync(0xffffffffu, l0, 2);
    l1 += __shfl_xor_sync(0xffffffffu, l1, 1);
    l1 += __shfl_xor_sync(0xffffffffu, l1, 2);

    const float il0 = 1.f / l0, il1 = 1.f / l1;
    const int rA = q0 + w * 16 + (lane >> 2);
    const size_t oA = ((size_t)b * SEQ + rA) * (NH * HD) + (size_t)h * HD + 2 * (lane & 3);
    const size_t oB = oA + (size_t)8 * (NH * HD);
#pragma unroll
    for (int j = 0; j < 16; j++) {
        uint32_t h01, lo01, h23, lo23;
        split2(o[j][0] * il0, o[j][1] * il0, h01, lo01);
        split2(o[j][2] * il1, o[j][3] * il1, h23, lo23);
        *(uint32_t*)&ohi[oA + j * 8] = h01;
        *(uint32_t*)&olo[oA + j * 8] = lo01;
        *(uint32_t*)&ohi[oB + j * 8] = h23;
        *(uint32_t*)&olo[oB + j * 8] = lo23;
    }
}

// ---------------------------------------------------------------------------
// Launcher
// ---------------------------------------------------------------------------
extern "C" void kernel_launch(void* const* d_in, const int* in_sizes, int n_in,
                              void* d_out, int out_size)
{
    const float* data = (const float*)d_in[0];
    const float* Wq   = (const float*)d_in[1];
    const float* Wk   = (const float*)d_in[2];
    const float* Wv   = (const float*)d_in[3];
    const float* Wo   = (const float*)d_in[4];
    const float* cosT = (const float*)d_in[5];
    const float* sinT = (const float*)d_in[6];
    float* out = (float*)d_out;
    (void)in_sizes; (void)n_in; (void)out_size;

    float *q, *k, *v;
    cudaGetSymbolAddress((void**)&q, g_q);
    cudaGetSymbolAddress((void**)&k, g_k);
    cudaGetSymbolAddress((void**)&v, g_v);

    __nv_bfloat16 *dh, *dl, *wqh, *wql, *wkh, *wkl, *wvh, *wvl, *woh, *wol, *ah, *al;
    __nv_bfloat16 *qsh, *qsl, *ksh, *ksl, *vsh, *vsl;
    cudaGetSymbolAddress((void**)&dh,  g_data_hi);
    cudaGetSymbolAddress((void**)&dl,  g_data_lo);
    cudaGetSymbolAddress((void**)&wqh, g_wq_hi);
    cudaGetSymbolAddress((void**)&wql, g_wq_lo);
    cudaGetSymbolAddress((void**)&wkh, g_wk_hi);
    cudaGetSymbolAddress((void**)&wkl, g_wk_lo);
    cudaGetSymbolAddress((void**)&wvh, g_wv_hi);
    cudaGetSymbolAddress((void**)&wvl, g_wv_lo);
    cudaGetSymbolAddress((void**)&woh, g_wo_hi);
    cudaGetSymbolAddress((void**)&wol, g_wo_lo);
    cudaGetSymbolAddress((void**)&ah,  g_attn_hi);
    cudaGetSymbolAddress((void**)&al,  g_attn_lo);
    cudaGetSymbolAddress((void**)&qsh, g_qs_hi);
    cudaGetSymbolAddress((void**)&qsl, g_qs_lo);
    cudaGetSymbolAddress((void**)&ksh, g_ks_hi);
    cudaGetSymbolAddress((void**)&ksl, g_ks_lo);
    cudaGetSymbolAddress((void**)&vsh, g_vs_hi);
    cudaGetSymbolAddress((void**)&vsl, g_vs_lo);

    cudaFuncSetAttribute(gemm_qkv,
                         cudaFuncAttributeMaxDynamicSharedMemorySize, GEMM_SMEM);
    cudaFuncSetAttribute(gemm_mm,
                         cudaFuncAttributeMaxDynamicSharedMemorySize, GEMM_SMEM);
    cudaFuncSetAttribute(flash_mma,
                         cudaFuncAttributeMaxDynamicSharedMemorySize, FLASH2_SMEM);

    // 1: all input splits in one launch
    split_all<<<(SPLIT_TOTAL + 255) / 256, 256>>>(data, Wq, Wk, Wv, Wo,
                                          dh, dl, wqh, wql, wkh, wkl, wvh, wvl, woh, wol);

    // 2: fused QKV projection (48 column tiles: 32 Q + 8 K + 8 V)
    gemm_qkv<<<dim3(48, TOKENS / 128), 256, GEMM_SMEM>>>(
        dh, dl, wqh, wql, wkh, wkl, wvh, wvl, q, k, v);

    // 3,4: RoPE + split (Q gets softmax scale * log2(e) for ex2-domain softmax)
    {
        const float qscale = 0.08838834764831845f * 1.4426950408889634f;
        int nq = TOKENS * NH * 64;
        rope_split<<<(nq + 255) / 256, 256>>>(q, qsh, qsl, cosT, sinT, NH, qscale);
        int nk = TOKENS * NKV * 64;
        rope_split<<<(nk + 255) / 256, 256>>>(k, ksh, ksl, cosT, sinT, NKV, 1.0f);
    }
    // 5: V split
    {
        int nv = TOKENS * (NKV * HD) / 4;
        split_bf16<<<(nv + 255) / 256, 256>>>(v, vsh, vsl, nv);
    }

    // 6: flash attention (ncu -s 5 -c 1 lands here)
    flash_mma<<<dim3(SEQ / 128, BATCH * NH), 256, FLASH2_SMEM>>>(
        qsh, qsl, ksh, ksl, vsh, vsl, ah, al);

    // 7: output projection
    gemm_mm<<<dim3(DIM / 128, TOKENS / 128), 256, GEMM_SMEM>>>(ah, al, woh, wol, out, DIM);
}

// round 9
// speedup vs baseline: 3.1838x; 1.0029x over previous
#include <cuda_runtime.h>
#include <cuda_bf16.h>
#include <math_constants.h>
#include <cstdint>

// Problem constants
#define BATCH 2
#define SEQ 2048
#define DIM 4096
#define NH 32
#define NKV 8
#define HD 128
#define TOKENS (BATCH * SEQ)   // 4096

// ---------------------------------------------------------------------------
// Scratch (device globals; no runtime allocation allowed)
// ---------------------------------------------------------------------------
__device__ __nv_bfloat16 g_data_hi[(size_t)TOKENS * DIM];
__device__ __nv_bfloat16 g_data_lo[(size_t)TOKENS * DIM];
__device__ __nv_bfloat16 g_wq_hi[(size_t)(NH * HD) * DIM];
__device__ __nv_bfloat16 g_wq_lo[(size_t)(NH * HD) * DIM];
__device__ __nv_bfloat16 g_wk_hi[(size_t)(NKV * HD) * DIM];
__device__ __nv_bfloat16 g_wk_lo[(size_t)(NKV * HD) * DIM];
__device__ __nv_bfloat16 g_wv_hi[(size_t)(NKV * HD) * DIM];
__device__ __nv_bfloat16 g_wv_lo[(size_t)(NKV * HD) * DIM];
__device__ __nv_bfloat16 g_wo_hi[(size_t)DIM * (NH * HD)];
__device__ __nv_bfloat16 g_wo_lo[(size_t)DIM * (NH * HD)];
__device__ __nv_bfloat16 g_attn_hi[(size_t)TOKENS * (NH * HD)];
__device__ __nv_bfloat16 g_attn_lo[(size_t)TOKENS * (NH * HD)];

// Post-RoPE split Q/K and split V (bf16 hi/lo) — written by gemm_qkv epilogue
__device__ __nv_bfloat16 g_qs_hi[(size_t)TOKENS * (NH * HD)];
__device__ __nv_bfloat16 g_qs_lo[(size_t)TOKENS * (NH * HD)];
__device__ __nv_bfloat16 g_ks_hi[(size_t)TOKENS * (NKV * HD)];
__device__ __nv_bfloat16 g_ks_lo[(size_t)TOKENS * (NKV * HD)];
__device__ __nv_bfloat16 g_vs_hi[(size_t)TOKENS * (NKV * HD)];
__device__ __nv_bfloat16 g_vs_lo[(size_t)TOKENS * (NKV * HD)];

// ---------------------------------------------------------------------------
// PTX helpers (compute_103-legal: ldmatrix / mma.sync / cp.async only)
// ---------------------------------------------------------------------------
__device__ __forceinline__ uint32_t smem_u32(const void* p) {
    uint32_t a;
    asm("{ .reg .u64 t; cvta.to.shared.u64 t, %1; cvt.u32.u64 %0, t; }"
        : "=r"(a) : "l"(p));
    return a;
}
__device__ __forceinline__ void cp16(uint32_t saddr, const void* g) {
    asm volatile("cp.async.cg.shared.global [%0], [%1], 16;" :: "r"(saddr), "l"(g));
}
__device__ __forceinline__ void ldm_x4(uint32_t* r, uint32_t addr) {
    asm volatile("ldmatrix.sync.aligned.m8n8.x4.shared.b16 {%0,%1,%2,%3}, [%4];"
                 : "=r"(r[0]), "=r"(r[1]), "=r"(r[2]), "=r"(r[3]) : "r"(addr));
}
__device__ __forceinline__ void ldm_x4t(uint32_t* r, uint32_t addr) {
    asm volatile("ldmatrix.sync.aligned.m8n8.x4.trans.shared.b16 {%0,%1,%2,%3}, [%4];"
                 : "=r"(r[0]), "=r"(r[1]), "=r"(r[2]), "=r"(r[3]) : "r"(addr));
}
__device__ __forceinline__ void mma16816(float* d, const uint32_t* a,
                                         uint32_t b0, uint32_t b1) {
    asm volatile(
        "mma.sync.aligned.m16n8k16.row.col.f32.bf16.bf16.f32 "
        "{%0,%1,%2,%3}, {%4,%5,%6,%7}, {%8,%9}, {%0,%1,%2,%3};"
        : "+f"(d[0]), "+f"(d[1]), "+f"(d[2]), "+f"(d[3])
        : "r"(a[0]), "r"(a[1]), "r"(a[2]), "r"(a[3]), "r"(b0), "r"(b1));
}
__device__ __forceinline__ float ex2(float x) {
    float r;
    asm("ex2.approx.f32 %0, %1;" : "=f"(r) : "f"(x));
    return r;
}
// RN-based split
__device__ __forceinline__ void split2(float a, float b, uint32_t& hi, uint32_t& lo) {
    __nv_bfloat16 ha = __float2bfloat16(a), hb = __float2bfloat16(b);
    __nv_bfloat162 H(ha, hb);
    __nv_bfloat162 L(__float2bfloat16(a - __bfloat162float(ha)),
                     __float2bfloat16(b - __bfloat162float(hb)));
    hi = *reinterpret_cast<uint32_t*>(&H);
    lo = *reinterpret_cast<uint32_t*>(&L);
}
// Truncation-based split (P in flash; hi+lo together keep full precision)
__device__ __forceinline__ void tsplit2(float a, float b, uint32_t& hi, uint32_t& lo) {
    uint32_t ua = __float_as_uint(a), ub = __float_as_uint(b);
    asm("prmt.b32 %0, %1, %2, 0x7632;" : "=r"(hi) : "r"(ua), "r"(ub));
    float ra = a - __uint_as_float(ua & 0xFFFF0000u);
    float rb = b - __uint_as_float(ub & 0xFFFF0000u);
    asm("cvt.rn.bf16x2.f32 %0, %1, %2;" : "=r"(lo) : "f"(rb), "f"(ra));
}

// ---------------------------------------------------------------------------
// HMMA GEMM core (tile 128x128, BK=32, 4-stage cp.async, 8 warps 4m x 2n)
// EPI: 0 = fp32 C, 1 = rope+scale+split -> Ohi/Olo, 2 = split-only -> Ohi/Olo
// ---------------------------------------------------------------------------
#define GK 4096
#define BKC 32
#define PASS_CHUNKS (GK / BKC)
#define NCHUNK (3 * PASS_CHUNKS)
#define STAGES 4
#define LDA 40
#define B_OFF_BYTES (128 * LDA * 2)
#define STAGE_BYTES (256 * LDA * 2)
#define GEMM_SMEM (STAGES * STAGE_BYTES)

__device__ __forceinline__ void load_chunk_mm(
    int c, uint32_t sbase, int tid, int m0, int n0,
    const __nv_bfloat16* __restrict__ Ahi, const __nv_bfloat16* __restrict__ Alo,
    const __nv_bfloat16* __restrict__ Bhi, const __nv_bfloat16* __restrict__ Blo)
{
    const int phase = c >> 7;
    const int kc = c & (PASS_CHUNKS - 1);
    const __nv_bfloat16* As = (phase < 2) ? Ahi : Alo;
    const __nv_bfloat16* Bs = (phase == 1) ? Blo : Bhi;
    const size_t ke = (size_t)kc * BKC;
    const int r0 = tid >> 2;
    const int seg = (tid & 3) * 8;
#pragma unroll
    for (int it = 0; it < 2; it++) {
        int r = r0 + it * 64;
        cp16(sbase + (uint32_t)(r * LDA + seg) * 2,
             As + (size_t)(m0 + r) * GK + ke + seg);
        cp16(sbase + B_OFF_BYTES + (uint32_t)(r * LDA + seg) * 2,
             Bs + (size_t)(n0 + r) * GK + ke + seg);
    }
    asm volatile("cp.async.commit_group;" ::: "memory");
}

template <int EPI>
__device__ __forceinline__ void gemm_core(
    const __nv_bfloat16* __restrict__ Ahi, const __nv_bfloat16* __restrict__ Alo,
    const __nv_bfloat16* __restrict__ Bhi, const __nv_bfloat16* __restrict__ Blo,
    float* __restrict__ C,
    __nv_bfloat16* __restrict__ Ohi, __nv_bfloat16* __restrict__ Olo,
    const float* __restrict__ cosT, const float* __restrict__ sinT, float scale,
    int Ng, int m0, int n0, char* dsm)
{
    const uint32_t base = smem_u32(dsm);
    const int tid = threadIdx.x;
    const int lane = tid & 31;
    const int w = tid >> 5;
    const int wm = (w >> 1) * 32;
    const int wn = (w & 1) * 64;

    float acc[2][8][4];
#pragma unroll
    for (int f = 0; f < 2; f++)
#pragma unroll
        for (int j = 0; j < 8; j++)
#pragma unroll
            for (int q = 0; q < 4; q++) acc[f][j][q] = 0.f;

    const uint32_t a_off = (uint32_t)(((lane & 15)) * LDA + ((lane >> 4) * 8)) * 2;
    const uint32_t b_off = (uint32_t)(((lane & 7) + ((lane >> 4) << 3)) * LDA
                                      + (((lane >> 3) & 1) * 8)) * 2;

#pragma unroll
    for (int s = 0; s < STAGES - 1; s++)
        load_chunk_mm(s, base + s * STAGE_BYTES, tid, m0, n0, Ahi, Alo, Bhi, Blo);

    for (int c = 0; c < NCHUNK; c++) {
        asm volatile("cp.async.wait_group %0;" :: "n"(STAGES - 2) : "memory");
        __syncthreads();

        const int ls = c + STAGES - 1;
        if (ls < NCHUNK)
            load_chunk_mm(ls, base + (ls & (STAGES - 1)) * STAGE_BYTES,
                          tid, m0, n0, Ahi, Alo, Bhi, Blo);
        else
            asm volatile("cp.async.commit_group;" ::: "memory");

        const uint32_t sb = base + (c & (STAGES - 1)) * STAGE_BYTES;
        const uint32_t a_base = sb + (uint32_t)(wm * LDA * 2) + a_off;
        const uint32_t b_base = sb + B_OFF_BYTES + (uint32_t)(wn * LDA * 2) + b_off;

#pragma unroll
        for (int ks = 0; ks < 2; ks++) {
            uint32_t a0[4], a1[4];
            ldm_x4(a0, a_base + ks * 32);
            ldm_x4(a1, a_base + ks * 32 + 16 * LDA * 2);
            uint32_t bf[4][4];
#pragma unroll
            for (int g = 0; g < 4; g++)
                ldm_x4(bf[g], b_base + ks * 32 + g * (16 * LDA * 2));
#pragma unroll
            for (int g = 0; g < 4; g++) {
                mma16816(acc[0][2 * g],     a0, bf[g][0], bf[g][1]);
                mma16816(acc[0][2 * g + 1], a0, bf[g][2], bf[g][3]);
                mma16816(acc[1][2 * g],     a1, bf[g][0], bf[g][1]);
                mma16816(acc[1][2 * g + 1], a1, bf[g][2], bf[g][3]);
            }
        }
    }

    const int gr = lane >> 2;
    const int gc = (lane & 3) * 2;

    if (EPI == 0) {
#pragma unroll
        for (int f = 0; f < 2; f++) {
            const int row = m0 + wm + f * 16 + gr;
#pragma unroll
            for (int j = 0; j < 8; j++) {
                const int col = n0 + wn + j * 8 + gc;
                *(float2*)&C[(size_t)row * Ng + col] =
                    make_float2(acc[f][j][0], acc[f][j][1]);
                *(float2*)&C[(size_t)(row + 8) * Ng + col] =
                    make_float2(acc[f][j][2], acc[f][j][3]);
            }
        }
    } else if (EPI == 2) {
        // Split-only epilogue (V): write bf16 hi/lo directly from regs
#pragma unroll
        for (int f = 0; f < 2; f++) {
            const int row = m0 + wm + f * 16 + gr;
#pragma unroll
            for (int j = 0; j < 8; j++) {
                const int col = n0 + wn + j * 8 + gc;
                uint32_t h, l;
                split2(acc[f][j][0], acc[f][j][1], h, l);
                *(uint32_t*)&Ohi[(size_t)row * Ng + col] = h;
                *(uint32_t*)&Olo[(size_t)row * Ng + col] = l;
                split2(acc[f][j][2], acc[f][j][3], h, l);
                *(uint32_t*)&Ohi[(size_t)(row + 8) * Ng + col] = h;
                *(uint32_t*)&Olo[(size_t)(row + 8) * Ng + col] = l;
            }
        }
    } else {
        // RoPE epilogue: tile columns = one head (128). Odd warps (wn=64) stash
        // their half (d in [64,128)) to smem; even warps combine pairs (d, d+64).
        __syncthreads();   // all ldmatrix of last stage done before smem reuse
        float* xs = (float*)dsm;   // [128][66]
        if (w & 1) {
#pragma unroll
            for (int f = 0; f < 2; f++) {
                const int rl = wm + f * 16 + gr;
#pragma unroll
                for (int j = 0; j < 8; j++) {
                    const int dd = j * 8 + gc;
                    xs[rl * 66 + dd]       = acc[f][j][0];
                    xs[rl * 66 + dd + 1]   = acc[f][j][1];
                    xs[(rl + 8) * 66 + dd]     = acc[f][j][2];
                    xs[(rl + 8) * 66 + dd + 1] = acc[f][j][3];
                }
            }
        }
        __syncthreads();
        if (!(w & 1)) {
#pragma unroll
            for (int f = 0; f < 2; f++) {
#pragma unroll
                for (int fr = 0; fr < 2; fr++) {
                    const int rl = wm + f * 16 + gr + fr * 8;
                    const int row = m0 + rl;
                    const int s = row & (SEQ - 1);
#pragma unroll
                    for (int j = 0; j < 8; j++) {
                        const int d = j * 8 + gc;
                        float x1a = acc[f][j][fr * 2];
                        float x1b = acc[f][j][fr * 2 + 1];
                        float x2a = xs[rl * 66 + d];
                        float x2b = xs[rl * 66 + d + 1];
                        float c0 = cosT[s * HD + d],     s0 = sinT[s * HD + d];
                        float c1 = cosT[s * HD + d + 1], s1 = sinT[s * HD + d + 1];
                        float y1a = (x1a * c0 - x2a * s0) * scale;
                        float y2a = (x2a * c0 + x1a * s0) * scale;
                        float y1b = (x1b * c1 - x2b * s1) * scale;
                        float y2b = (x2b * c1 + x1b * s1) * scale;
                        uint32_t h, l;
                        split2(y1a, y1b, h, l);
                        *(uint32_t*)&Ohi[(size_t)row * Ng + n0 + d] = h;
                        *(uint32_t*)&Olo[(size_t)row * Ng + n0 + d] = l;
                        split2(y2a, y2b, h, l);
                        *(uint32_t*)&Ohi[(size_t)row * Ng + n0 + 64 + d] = h;
                        *(uint32_t*)&Olo[(size_t)row * Ng + n0 + 64 + d] = l;
                    }
                }
            }
        }
    }
}

#define QSCALE (0.08838834764831845f * 1.4426950408889634f)

// Fused QKV projection + RoPE + split: bx 0..31 Q, 32..39 K, 40..47 V
__global__ __launch_bounds__(256, 2) void gemm_qkv(
    const __nv_bfloat16* __restrict__ dh, const __nv_bfloat16* __restrict__ dl,
    const __nv_bfloat16* __restrict__ wqh, const __nv_bfloat16* __restrict__ wql,
    const __nv_bfloat16* __restrict__ wkh, const __nv_bfloat16* __restrict__ wkl,
    const __nv_bfloat16* __restrict__ wvh, const __nv_bfloat16* __restrict__ wvl,
    __nv_bfloat16* __restrict__ qsh, __nv_bfloat16* __restrict__ qsl,
    __nv_bfloat16* __restrict__ ksh, __nv_bfloat16* __restrict__ ksl,
    __nv_bfloat16* __restrict__ vsh, __nv_bfloat16* __restrict__ vsl,
    const float* __restrict__ cosT, const float* __restrict__ sinT)
{
    extern __shared__ char dsm[];
    const int bx = blockIdx.x;
    const int m0 = blockIdx.y * 128;
    if (bx < 32) {
        gemm_core<1>(dh, dl, wqh, wql, nullptr, qsh, qsl, cosT, sinT, QSCALE,
                     NH * HD, m0, bx * 128, dsm);
    } else if (bx < 40) {
        gemm_core<1>(dh, dl, wkh, wkl, nullptr, ksh, ksl, cosT, sinT, 1.0f,
                     NKV * HD, m0, (bx - 32) * 128, dsm);
    } else {
        gemm_core<2>(dh, dl, wvh, wvl, nullptr, vsh, vsl, nullptr, nullptr, 1.0f,
                     NKV * HD, m0, (bx - 40) * 128, dsm);
    }
}

// O projection (plain fp32 epilogue)
__global__ __launch_bounds__(256, 2) void gemm_mm(
    const __nv_bfloat16* __restrict__ Ahi, const __nv_bfloat16* __restrict__ Alo,
    const __nv_bfloat16* __restrict__ Bhi, const __nv_bfloat16* __restrict__ Blo,
    float* __restrict__ C, int Ng)
{
    extern __shared__ char dsm[];
    gemm_core<0>(Ahi, Alo, Bhi, Blo, C, nullptr, nullptr, nullptr, nullptr, 1.0f,
                 Ng, blockIdx.y * 128, blockIdx.x * 128, dsm);
}

// ---------------------------------------------------------------------------
// One fused split kernel for all 5 fp32 inputs (sizes in float4 units)
// ---------------------------------------------------------------------------
#define SPLIT_N_DATA  4194304
#define SPLIT_N_WQ    4194304
#define SPLIT_N_WK    1048576
#define SPLIT_N_WV    1048576
#define SPLIT_N_WO    4194304
#define SPLIT_TOTAL   (SPLIT_N_DATA + SPLIT_N_WQ + SPLIT_N_WK + SPLIT_N_WV + SPLIT_N_WO)

__global__ void split_all(
    const float* __restrict__ data, const float* __restrict__ Wq,
    const float* __restrict__ Wk, const float* __restrict__ Wv,
    const float* __restrict__ Wo,
    __nv_bfloat16* __restrict__ dh, __nv_bfloat16* __restrict__ dl,
    __nv_bfloat16* __restrict__ qh, __nv_bfloat16* __restrict__ ql,
    __nv_bfloat16* __restrict__ kh, __nv_bfloat16* __restrict__ kl,
    __nv_bfloat16* __restrict__ vh, __nv_bfloat16* __restrict__ vl,
    __nv_bfloat16* __restrict__ oh, __nv_bfloat16* __restrict__ ol)
{
    int i = blockIdx.x * 256 + threadIdx.x;
    if (i >= SPLIT_TOTAL) return;
    const float* src; __nv_bfloat16 *hi, *lo; int off;
    if (i < SPLIT_N_DATA) { src = data; hi = dh; lo = dl; off = 0; }
    else if (i < SPLIT_N_DATA + SPLIT_N_WQ)
        { src = Wq; hi = qh; lo = ql; off = SPLIT_N_DATA; }
    else if (i < SPLIT_N_DATA + SPLIT_N_WQ + SPLIT_N_WK)
        { src = Wk; hi = kh; lo = kl; off = SPLIT_N_DATA + SPLIT_N_WQ; }
    else if (i < SPLIT_N_DATA + SPLIT_N_WQ + SPLIT_N_WK + SPLIT_N_WV)
        { src = Wv; hi = vh; lo = vl; off = SPLIT_N_DATA + SPLIT_N_WQ + SPLIT_N_WK; }
    else
        { src = Wo; hi = oh; lo = ol; off = SPLIT_N_DATA + SPLIT_N_WQ + SPLIT_N_WK + SPLIT_N_WV; }
    int j = i - off;
    float4 val = ((const float4*)src)[j];
    uint32_t h01, l01, h23, l23;
    split2(val.x, val.y, h01, l01);
    split2(val.z, val.w, h23, l23);
    ((uint32_t*)hi)[j * 2]     = h01;
    ((uint32_t*)hi)[j * 2 + 1] = h23;
    ((uint32_t*)lo)[j * 2]     = l01;
    ((uint32_t*)lo)[j * 2 + 1] = l23;
}

// ---------------------------------------------------------------------------
// Flash attention on HMMA. BQ=128, BKV=64, 8 warps x 16 q-rows.
// Fixed S accumulator chains (ks-outer), single-phase softmax per tile.
// ---------------------------------------------------------------------------
#define LDV 136
#define LDVB (LDV * 2)
#define FBUF (64 * LDVB)
#define FSTG (4 * FBUF)
#define FLASH2_SMEM (2 * FSTG)

__device__ __forceinline__ void load_kv(uint32_t sb, int tid,
    const __nv_bfloat16* __restrict__ khi, const __nv_bfloat16* __restrict__ klo,
    const __nv_bfloat16* __restrict__ vhi, const __nv_bfloat16* __restrict__ vlo,
    size_t kvbase)
{
#pragma unroll
    for (int i = 0; i < 4; i++) {
        int idx = tid + i * 256;
        int r = idx >> 4, sg = idx & 15;
        size_t g = kvbase + (size_t)r * (NKV * HD) + sg * 8;
        uint32_t s = sb + r * LDVB + sg * 16;
        cp16(s,            khi + g);
        cp16(s + FBUF,     klo + g);
        cp16(s + 2 * FBUF, vhi + g);
        cp16(s + 3 * FBUF, vlo + g);
    }
    asm volatile("cp.async.commit_group;" ::: "memory");
}

__global__ __launch_bounds__(256) void flash_mma(
    const __nv_bfloat16* __restrict__ qhi, const __nv_bfloat16* __restrict__ qlo,
    const __nv_bfloat16* __restrict__ khi, const __nv_bfloat16* __restrict__ klo,
    const __nv_bfloat16* __restrict__ vhi, const __nv_bfloat16* __restrict__ vlo,
    __nv_bfloat16* __restrict__ ohi, __nv_bfloat16* __restrict__ olo)
{
    extern __shared__ char dsm[];
    const uint32_t base = smem_u32(dsm);
    const int tid = threadIdx.x;
    const int lane = tid & 31;
    const int w = tid >> 5;
    const int qb = gridDim.x - 1 - blockIdx.x;   // heavy tiles first
    const int bh = blockIdx.y;
    const int b = bh / NH, h = bh % NH;
    const int kh = h / (NH / NKV);
    const int q0 = qb * 128;

    const size_t qbase = ((size_t)b * SEQ + q0) * (NH * HD) + (size_t)h * HD;
    const size_t kvh   = ((size_t)b * SEQ) * (NKV * HD) + (size_t)kh * HD;

    // Stage Q through stage-0 smem, extract frags to regs
#pragma unroll
    for (int i = 0; i < 8; i++) {
        int idx = tid + i * 256;
        int r = idx >> 4, sg = idx & 15;
        size_t g = qbase + (size_t)r * (NH * HD) + sg * 8;
        cp16(base + r * LDVB + sg * 16,            qhi + g);
        cp16(base + 2 * FBUF + r * LDVB + sg * 16, qlo + g);
    }
    asm volatile("cp.async.commit_group;" ::: "memory");
    asm volatile("cp.async.wait_group 0;" ::: "memory");
    __syncthreads();

    uint32_t qa_h[8][4], qa_l[8][4];
    {
        const uint32_t qrow = base + (w * 16 + (lane & 15)) * LDVB + (lane >> 4) * 16;
#pragma unroll
        for (int ks = 0; ks < 8; ks++) {
            ldm_x4(qa_h[ks], qrow + ks * 32);
            ldm_x4(qa_l[ks], qrow + 2 * FBUF + ks * 32);
        }
    }
    __syncthreads();

    float o[16][4];
#pragma unroll
    for (int j = 0; j < 16; j++)
#pragma unroll
        for (int q = 0; q < 4; q++) o[j][q] = 0.f;
    float m0 = -CUDART_INF_F, m1 = -CUDART_INF_F, l0 = 0.f, l1 = 0.f;

    const int n = 2 * (qb + 1);
    load_kv(base, tid, khi, klo, vhi, vlo, kvh);

    const uint32_t koff = ((lane & 7) + ((lane >> 4) << 3)) * LDVB + ((lane >> 3) & 1) * 16;
    const uint32_t voff = (lane & 15) * LDVB + (lane >> 4) * 16;

    for (int t = 0; t < n; t++) {
        asm volatile("cp.async.wait_group 0;" ::: "memory");
        __syncthreads();
        if (t + 1 < n)
            load_kv(base + ((t + 1) & 1) * FSTG, tid, khi, klo, vhi, vlo,
                    kvh + (size_t)(t + 1) * 64 * (NKV * HD));

        const uint32_t sb = base + (t & 1) * FSTG;
        const uint32_t vbh = sb + 2 * FBUF + voff;

        // S = Q K^T  (ks-outer: 8 independent accumulators per step)
        float s[8][4];
#pragma unroll
        for (int f = 0; f < 8; f++)
#pragma unroll
            for (int q = 0; q < 4; q++) s[f][q] = 0.f;

#pragma unroll
        for (int ks = 0; ks < 8; ks++) {
#pragma unroll
            for (int g = 0; g < 4; g++) {
                uint32_t kbh[4], kbl[4];
                ldm_x4(kbh, sb + g * 16 * LDVB + ks * 32 + koff);
                ldm_x4(kbl, sb + FBUF + g * 16 * LDVB + ks * 32 + koff);
                mma16816(s[2 * g],     qa_h[ks], kbh[0], kbh[1]);
                mma16816(s[2 * g + 1], qa_h[ks], kbh[2], kbh[3]);
                mma16816(s[2 * g],     qa_h[ks], kbl[0], kbl[1]);
                mma16816(s[2 * g + 1], qa_h[ks], kbl[2], kbl[3]);
                mma16816(s[2 * g],     qa_l[ks], kbh[0], kbh[1]);
                mma16816(s[2 * g + 1], qa_l[ks], kbh[2], kbh[3]);
            }
        }

        // Causal mask (last two kv tiles)
        if (t >= n - 2) {
            const int rA = q0 + w * 16 + (lane >> 2);
            const int cb = t * 64 + 2 * (lane & 3);
#pragma unroll
            for (int f = 0; f < 8; f++) {
                int c = cb + f * 8;
                if (c > rA)         s[f][0] = -1e30f;
                if (c + 1 > rA)     s[f][1] = -1e30f;
                if (c > rA + 8)     s[f][2] = -1e30f;
                if (c + 1 > rA + 8) s[f][3] = -1e30f;
            }
        }

        // Single-phase online softmax over all 64 cols
        float mn0 = m0, mn1 = m1;
#pragma unroll
        for (int f = 0; f < 8; f++) {
            mn0 = fmaxf(mn0, fmaxf(s[f][0], s[f][1]));
            mn1 = fmaxf(mn1, fmaxf(s[f][2], s[f][3]));
        }
        mn0 = fmaxf(mn0, __shfl_xor_sync(0xffffffffu, mn0, 1));
        mn0 = fmaxf(mn0, __shfl_xor_sync(0xffffffffu, mn0, 2));
        mn1 = fmaxf(mn1, __shfl_xor_sync(0xffffffffu, mn1, 1));
        mn1 = fmaxf(mn1, __shfl_xor_sync(0xffffffffu, mn1, 2));
        const float cr0 = ex2(m0 - mn0), cr1 = ex2(m1 - mn1);
        m0 = mn0; m1 = mn1;
        l0 *= cr0; l1 *= cr1;
#pragma unroll
        for (int j = 0; j < 16; j++) {
            o[j][0] *= cr0; o[j][1] *= cr0;
            o[j][2] *= cr1; o[j][3] *= cr1;
        }

        float rs0 = 0.f, rs1 = 0.f;
        uint32_t ph01[8], ph23[8], pl01[8], pl23[8];
#pragma unroll
        for (int f = 0; f < 8; f++) {
            float p0 = ex2(s[f][0] - m0);
            float p1 = ex2(s[f][1] - m0);
            float p2 = ex2(s[f][2] - m1);
            float p3 = ex2(s[f][3] - m1);
            rs0 += p0 + p1;
            rs1 += p2 + p3;
            tsplit2(p0, p1, ph01[f], pl01[f]);
            tsplit2(p2, p3, ph23[f], pl23[f]);
        }
        l0 += rs0;   // per-lane partial; cross-lane reduced after the loop
        l1 += rs1;

        // O += P V (3 terms), kc-outer / g-inner (16 accumulators per kc)
#pragma unroll
        for (int kc = 0; kc < 4; kc++) {
            uint32_t ah[4] = {ph01[2 * kc], ph23[2 * kc],
                              ph01[2 * kc + 1], ph23[2 * kc + 1]};
            uint32_t al[4] = {pl01[2 * kc], pl23[2 * kc],
                              pl01[2 * kc + 1], pl23[2 * kc + 1]};
#pragma unroll
            for (int g = 0; g < 8; g++) {
                uint32_t vh4[4], vl4[4];
                ldm_x4t(vh4, vbh + kc * 16 * LDVB + g * 32);
                ldm_x4t(vl4, vbh + FBUF + kc * 16 * LDVB + g * 32);
                mma16816(o[2 * g],     ah, vh4[0], vh4[1]);
                mma16816(o[2 * g + 1], ah, vh4[2], vh4[3]);
                mma16816(o[2 * g],     ah, vl4[0], vl4[1]);
                mma16816(o[2 * g + 1], ah, vl4[2], vl4[3]);
                mma16816(o[2 * g],     al, vh4[0], vh4[1]);
                mma16816(o[2 * g + 1], al, vh4[2], vh4[3]);
            }
        }
    }

    // Deferred cross-lane l reduction
    l0 += __shfl_xor_sync(0xffffffffu, l0, 1);
    l0 += __shfl_xor_sync(0xffffffffu, l0, 2);
    l1 += __shfl_xor_sync(0xffffffffu, l1, 1);
    l1 += __shfl_xor_sync(0xffffffffu, l1, 2);

    const float il0 = 1.f / l0, il1 = 1.f / l1;
    const int rA = q0 + w * 16 + (lane >> 2);
    const size_t oA = ((size_t)b * SEQ + rA) * (NH * HD) + (size_t)h * HD + 2 * (lane & 3);
    const size_t oB = oA + (size_t)8 * (NH * HD);
#pragma unroll
    for (int j = 0; j < 16; j++) {
        uint32_t h01, lo01, h23, lo23;
        split2(o[j][0] * il0, o[j][1] * il0, h01, lo01);
        split2(o[j][2] * il1, o[j][3] * il1, h23, lo23);
        *(uint32_t*)&ohi[oA + j * 8] = h01;
        *(uint32_t*)&olo[oA + j * 8] = lo01;
        *(uint32_t*)&ohi[oB + j * 8] = h23;
        *(uint32_t*)&olo[oB + j * 8] = lo23;
    }
}

// ---------------------------------------------------------------------------
// Launcher
// ---------------------------------------------------------------------------
extern "C" void kernel_launch(void* const* d_in, const int* in_sizes, int n_in,
                              void* d_out, int out_size)
{
    const float* data = (const float*)d_in[0];
    const float* Wq   = (const float*)d_in[1];
    const float* Wk   = (const float*)d_in[2];
    const float* Wv   = (const float*)d_in[3];
    const float* Wo   = (const float*)d_in[4];
    const float* cosT = (const float*)d_in[5];
    const float* sinT = (const float*)d_in[6];
    float* out = (float*)d_out;
    (void)in_sizes; (void)n_in; (void)out_size;

    __nv_bfloat16 *dh, *dl, *wqh, *wql, *wkh, *wkl, *wvh, *wvl, *woh, *wol, *ah, *al;
    __nv_bfloat16 *qsh, *qsl, *ksh, *ksl, *vsh, *vsl;
    cudaGetSymbolAddress((void**)&dh,  g_data_hi);
    cudaGetSymbolAddress((void**)&dl,  g_data_lo);
    cudaGetSymbolAddress((void**)&wqh, g_wq_hi);
    cudaGetSymbolAddress((void**)&wql, g_wq_lo);
    cudaGetSymbolAddress((void**)&wkh, g_wk_hi);
    cudaGetSymbolAddress((void**)&wkl, g_wk_lo);
    cudaGetSymbolAddress((void**)&wvh, g_wv_hi);
    cudaGetSymbolAddress((void**)&wvl, g_wv_lo);
    cudaGetSymbolAddress((void**)&woh, g_wo_hi);
    cudaGetSymbolAddress((void**)&wol, g_wo_lo);
    cudaGetSymbolAddress((void**)&ah,  g_attn_hi);
    cudaGetSymbolAddress((void**)&al,  g_attn_lo);
    cudaGetSymbolAddress((void**)&qsh, g_qs_hi);
    cudaGetSymbolAddress((void**)&qsl, g_qs_lo);
    cudaGetSymbolAddress((void**)&ksh, g_ks_hi);
    cudaGetSymbolAddress((void**)&ksl, g_ks_lo);
    cudaGetSymbolAddress((void**)&vsh, g_vs_hi);
    cudaGetSymbolAddress((void**)&vsl, g_vs_lo);

    cudaFuncSetAttribute(gemm_qkv,
                         cudaFuncAttributeMaxDynamicSharedMemorySize, GEMM_SMEM);
    cudaFuncSetAttribute(gemm_mm,
                         cudaFuncAttributeMaxDynamicSharedMemorySize, GEMM_SMEM);
    cudaFuncSetAttribute(flash_mma,
                         cudaFuncAttributeMaxDynamicSharedMemorySize, FLASH2_SMEM);

    // 1: all input splits
    split_all<<<(SPLIT_TOTAL + 255) / 256, 256>>>(data, Wq, Wk, Wv, Wo,
                                          dh, dl, wqh, wql, wkh, wkl, wvh, wvl, woh, wol);

    // 2: fused QKV projection + RoPE + split (48 column tiles)
    gemm_qkv<<<dim3(48, TOKENS / 128), 256, GEMM_SMEM>>>(
        dh, dl, wqh, wql, wkh, wkl, wvh, wvl,
        qsh, qsl, ksh, ksl, vsh, vsl, cosT, sinT);

    // 3: flash attention (writes bf16 hi/lo)
    flash_mma<<<dim3(SEQ / 128, BATCH * NH), 256, FLASH2_SMEM>>>(
        qsh, qsl, ksh, ksl, vsh, vsl, ah, al);

    // 4: output projection
    gemm_mm<<<dim3(DIM / 128, TOKENS / 128), 256, GEMM_SMEM>>>(ah, al, woh, wol, out, DIM);
}

// round 10
// speedup vs baseline: 3.5627x; 1.1190x over previous
#include <cuda_runtime.h>
#include <cuda_bf16.h>
#include <math_constants.h>
#include <cstdint>

// Problem constants
#define BATCH 2
#define SEQ 2048
#define DIM 4096
#define NH 32
#define NKV 8
#define HD 128
#define TOKENS (BATCH * SEQ)   // 4096

// ---------------------------------------------------------------------------
// Scratch (device globals; no runtime allocation allowed)
// ---------------------------------------------------------------------------
__device__ __nv_bfloat16 g_data_hi[(size_t)TOKENS * DIM];
__device__ __nv_bfloat16 g_data_lo[(size_t)TOKENS * DIM];
__device__ __nv_bfloat16 g_wq_hi[(size_t)(NH * HD) * DIM];
__device__ __nv_bfloat16 g_wq_lo[(size_t)(NH * HD) * DIM];
__device__ __nv_bfloat16 g_wk_hi[(size_t)(NKV * HD) * DIM];
__device__ __nv_bfloat16 g_wk_lo[(size_t)(NKV * HD) * DIM];
__device__ __nv_bfloat16 g_wv_hi[(size_t)(NKV * HD) * DIM];
__device__ __nv_bfloat16 g_wv_lo[(size_t)(NKV * HD) * DIM];
__device__ __nv_bfloat16 g_wo_hi[(size_t)DIM * (NH * HD)];
__device__ __nv_bfloat16 g_wo_lo[(size_t)DIM * (NH * HD)];
__device__ __nv_bfloat16 g_attn_hi[(size_t)TOKENS * (NH * HD)];
__device__ __nv_bfloat16 g_attn_lo[(size_t)TOKENS * (NH * HD)];

// Post-RoPE split Q/K and split V (bf16 hi/lo) — written by gemm_qkv epilogue
__device__ __nv_bfloat16 g_qs_hi[(size_t)TOKENS * (NH * HD)];
__device__ __nv_bfloat16 g_qs_lo[(size_t)TOKENS * (NH * HD)];
__device__ __nv_bfloat16 g_ks_hi[(size_t)TOKENS * (NKV * HD)];
__device__ __nv_bfloat16 g_ks_lo[(size_t)TOKENS * (NKV * HD)];
__device__ __nv_bfloat16 g_vs_hi[(size_t)TOKENS * (NKV * HD)];
__device__ __nv_bfloat16 g_vs_lo[(size_t)TOKENS * (NKV * HD)];

// ---------------------------------------------------------------------------
// PTX helpers (compute_103-legal: ldmatrix / mma.sync / cp.async only)
// ---------------------------------------------------------------------------
__device__ __forceinline__ uint32_t smem_u32(const void* p) {
    uint32_t a;
    asm("{ .reg .u64 t; cvta.to.shared.u64 t, %1; cvt.u32.u64 %0, t; }"
        : "=r"(a) : "l"(p));
    return a;
}
__device__ __forceinline__ void cp16(uint32_t saddr, const void* g) {
    asm volatile("cp.async.cg.shared.global [%0], [%1], 16;" :: "r"(saddr), "l"(g));
}
__device__ __forceinline__ void ldm_x4(uint32_t* r, uint32_t addr) {
    asm volatile("ldmatrix.sync.aligned.m8n8.x4.shared.b16 {%0,%1,%2,%3}, [%4];"
                 : "=r"(r[0]), "=r"(r[1]), "=r"(r[2]), "=r"(r[3]) : "r"(addr));
}
__device__ __forceinline__ void ldm_x4t(uint32_t* r, uint32_t addr) {
    asm volatile("ldmatrix.sync.aligned.m8n8.x4.trans.shared.b16 {%0,%1,%2,%3}, [%4];"
                 : "=r"(r[0]), "=r"(r[1]), "=r"(r[2]), "=r"(r[3]) : "r"(addr));
}
__device__ __forceinline__ void mma16816(float* d, const uint32_t* a,
                                         uint32_t b0, uint32_t b1) {
    asm volatile(
        "mma.sync.aligned.m16n8k16.row.col.f32.bf16.bf16.f32 "
        "{%0,%1,%2,%3}, {%4,%5,%6,%7}, {%8,%9}, {%0,%1,%2,%3};"
        : "+f"(d[0]), "+f"(d[1]), "+f"(d[2]), "+f"(d[3])
        : "r"(a[0]), "r"(a[1]), "r"(a[2]), "r"(a[3]), "r"(b0), "r"(b1));
}
__device__ __forceinline__ float ex2(float x) {
    float r;
    asm("ex2.approx.f32 %0, %1;" : "=f"(r) : "f"(x));
    return r;
}
// RN-based split
__device__ __forceinline__ void split2(float a, float b, uint32_t& hi, uint32_t& lo) {
    __nv_bfloat16 ha = __float2bfloat16(a), hb = __float2bfloat16(b);
    __nv_bfloat162 H(ha, hb);
    __nv_bfloat162 L(__float2bfloat16(a - __bfloat162float(ha)),
                     __float2bfloat16(b - __bfloat162float(hb)));
    hi = *reinterpret_cast<uint32_t*>(&H);
    lo = *reinterpret_cast<uint32_t*>(&L);
}
// Truncation-based split (P in flash; hi+lo together keep full precision)
__device__ __forceinline__ void tsplit2(float a, float b, uint32_t& hi, uint32_t& lo) {
    uint32_t ua = __float_as_uint(a), ub = __float_as_uint(b);
    asm("prmt.b32 %0, %1, %2, 0x7632;" : "=r"(hi) : "r"(ua), "r"(ub));
    float ra = a - __uint_as_float(ua & 0xFFFF0000u);
    float rb = b - __uint_as_float(ub & 0xFFFF0000u);
    asm("cvt.rn.bf16x2.f32 %0, %1, %2;" : "=r"(lo) : "f"(rb), "f"(ra));
}

// ---------------------------------------------------------------------------
// HMMA GEMM core, 3 split terms per chunk (hh + lh + hl from one stage).
// Tile 128x128, BK=32, 2-stage cp.async (40KB/stage), 8 warps 4m x 2n.
// EPI: 0 = fp32 C, 1 = rope+scale+split -> Ohi/Olo, 2 = split-only -> Ohi/Olo
// ---------------------------------------------------------------------------
#define GK 4096
#define BKC 32
#define NCHUNK2 (GK / BKC)           // 128
#define LDA 40
#define ABUF_B (128 * LDA * 2)       // 10240 B per array
#define OFF_AL ABUF_B
#define OFF_BH (2 * ABUF_B)
#define OFF_BL (3 * ABUF_B)
#define STAGE2_BYTES (4 * ABUF_B)    // 40960
#define GEMM_SMEM (2 * STAGE2_BYTES) // 81920

__device__ __forceinline__ void load_chunk_mm(
    int kc, uint32_t sbase, int tid, int m0, int n0,
    const __nv_bfloat16* __restrict__ Ahi, const __nv_bfloat16* __restrict__ Alo,
    const __nv_bfloat16* __restrict__ Bhi, const __nv_bfloat16* __restrict__ Blo)
{
    const size_t ke = (size_t)kc * BKC;
    const int r0 = tid >> 2;             // 0..63
    const int seg = (tid & 3) * 8;       // elem offset within 32-elem row
#pragma unroll
    for (int it = 0; it < 2; it++) {
        int r = r0 + it * 64;
        uint32_t srow = sbase + (uint32_t)(r * LDA + seg) * 2;
        size_t ga = (size_t)(m0 + r) * GK + ke + seg;
        size_t gb = (size_t)(n0 + r) * GK + ke + seg;
        cp16(srow,          Ahi + ga);
        cp16(srow + OFF_AL, Alo + ga);
        cp16(srow + OFF_BH, Bhi + gb);
        cp16(srow + OFF_BL, Blo + gb);
    }
    asm volatile("cp.async.commit_group;" ::: "memory");
}

template <int EPI>
__device__ __forceinline__ void gemm_core(
    const __nv_bfloat16* __restrict__ Ahi, const __nv_bfloat16* __restrict__ Alo,
    const __nv_bfloat16* __restrict__ Bhi, const __nv_bfloat16* __restrict__ Blo,
    float* __restrict__ C,
    __nv_bfloat16* __restrict__ Ohi, __nv_bfloat16* __restrict__ Olo,
    const float* __restrict__ cosT, const float* __restrict__ sinT, float scale,
    int Ng, int m0, int n0, char* dsm)
{
    const uint32_t base = smem_u32(dsm);
    const int tid = threadIdx.x;
    const int lane = tid & 31;
    const int w = tid >> 5;
    const int wm = (w >> 1) * 32;
    const int wn = (w & 1) * 64;

    float acc[2][8][4];
#pragma unroll
    for (int f = 0; f < 2; f++)
#pragma unroll
        for (int j = 0; j < 8; j++)
#pragma unroll
            for (int q = 0; q < 4; q++) acc[f][j][q] = 0.f;

    const uint32_t a_off = (uint32_t)(((lane & 15)) * LDA + ((lane >> 4) * 8)) * 2;
    const uint32_t b_off = (uint32_t)(((lane & 7) + ((lane >> 4) << 3)) * LDA
                                      + (((lane >> 3) & 1) * 8)) * 2;

    load_chunk_mm(0, base, tid, m0, n0, Ahi, Alo, Bhi, Blo);

    for (int c = 0; c < NCHUNK2; c++) {
        if (c + 1 < NCHUNK2)
            load_chunk_mm(c + 1, base + ((c + 1) & 1) * STAGE2_BYTES,
                          tid, m0, n0, Ahi, Alo, Bhi, Blo);
        else
            asm volatile("cp.async.commit_group;" ::: "memory");
        asm volatile("cp.async.wait_group 1;" ::: "memory");
        __syncthreads();

        const uint32_t sb = base + (c & 1) * STAGE2_BYTES;
        const uint32_t abh = sb + (uint32_t)(wm * LDA * 2) + a_off;
        const uint32_t bbh = sb + OFF_BH + (uint32_t)(wn * LDA * 2) + b_off;

#pragma unroll
        for (int ks = 0; ks < 2; ks++) {
            uint32_t a0h[4], a1h[4], a0l[4], a1l[4];
            ldm_x4(a0h, abh + ks * 32);
            ldm_x4(a1h, abh + ks * 32 + 16 * LDA * 2);
            ldm_x4(a0l, abh + OFF_AL + ks * 32);
            ldm_x4(a1l, abh + OFF_AL + ks * 32 + 16 * LDA * 2);
#pragma unroll
            for (int g = 0; g < 4; g++) {
                uint32_t bh[4];
                ldm_x4(bh, bbh + ks * 32 + g * (16 * LDA * 2));
                // hh
                mma16816(acc[0][2 * g],     a0h, bh[0], bh[1]);
                mma16816(acc[0][2 * g + 1], a0h, bh[2], bh[3]);
                mma16816(acc[1][2 * g],     a1h, bh[0], bh[1]);
                mma16816(acc[1][2 * g + 1], a1h, bh[2], bh[3]);
                // lh
                mma16816(acc[0][2 * g],     a0l, bh[0], bh[1]);
                mma16816(acc[0][2 * g + 1], a0l, bh[2], bh[3]);
                mma16816(acc[1][2 * g],     a1l, bh[0], bh[1]);
                mma16816(acc[1][2 * g + 1], a1l, bh[2], bh[3]);
                // hl (load B-lo after B-hi uses so regs can be reused)
                uint32_t bl[4];
                ldm_x4(bl, bbh + (OFF_BL - OFF_BH) + ks * 32 + g * (16 * LDA * 2));
                mma16816(acc[0][2 * g],     a0h, bl[0], bl[1]);
                mma16816(acc[0][2 * g + 1], a0h, bl[2], bl[3]);
                mma16816(acc[1][2 * g],     a1h, bl[0], bl[1]);
                mma16816(acc[1][2 * g + 1], a1h, bl[2], bl[3]);
            }
        }
        __syncthreads();
    }

    const int gr = lane >> 2;
    const int gc = (lane & 3) * 2;

    if (EPI == 0) {
#pragma unroll
        for (int f = 0; f < 2; f++) {
            const int row = m0 + wm + f * 16 + gr;
#pragma unroll
            for (int j = 0; j < 8; j++) {
                const int col = n0 + wn + j * 8 + gc;
                *(float2*)&C[(size_t)row * Ng + col] =
                    make_float2(acc[f][j][0], acc[f][j][1]);
                *(float2*)&C[(size_t)(row + 8) * Ng + col] =
                    make_float2(acc[f][j][2], acc[f][j][3]);
            }
        }
    } else if (EPI == 2) {
        // Split-only epilogue (V): write bf16 hi/lo directly from regs
#pragma unroll
        for (int f = 0; f < 2; f++) {
            const int row = m0 + wm + f * 16 + gr;
#pragma unroll
            for (int j = 0; j < 8; j++) {
                const int col = n0 + wn + j * 8 + gc;
                uint32_t h, l;
                split2(acc[f][j][0], acc[f][j][1], h, l);
                *(uint32_t*)&Ohi[(size_t)row * Ng + col] = h;
                *(uint32_t*)&Olo[(size_t)row * Ng + col] = l;
                split2(acc[f][j][2], acc[f][j][3], h, l);
                *(uint32_t*)&Ohi[(size_t)(row + 8) * Ng + col] = h;
                *(uint32_t*)&Olo[(size_t)(row + 8) * Ng + col] = l;
            }
        }
    } else {
        // RoPE epilogue: tile columns = one head (128). Odd warps (wn=64) stash
        // their half (d in [64,128)) to smem; even warps combine pairs (d, d+64).
        __syncthreads();   // all ldmatrix of last stage done before smem reuse
        float* xs = (float*)dsm;   // [128][66]
        if (w & 1) {
#pragma unroll
            for (int f = 0; f < 2; f++) {
                const int rl = wm + f * 16 + gr;
#pragma unroll
                for (int j = 0; j < 8; j++) {
                    const int dd = j * 8 + gc;
                    xs[rl * 66 + dd]       = acc[f][j][0];
                    xs[rl * 66 + dd + 1]   = acc[f][j][1];
                    xs[(rl + 8) * 66 + dd]     = acc[f][j][2];
                    xs[(rl + 8) * 66 + dd + 1] = acc[f][j][3];
                }
            }
        }
        __syncthreads();
        if (!(w & 1)) {
#pragma unroll
            for (int f = 0; f < 2; f++) {
#pragma unroll
                for (int fr = 0; fr < 2; fr++) {
                    const int rl = wm + f * 16 + gr + fr * 8;
                    const int row = m0 + rl;
                    const int s = row & (SEQ - 1);
#pragma unroll
                    for (int j = 0; j < 8; j++) {
                        const int d = j * 8 + gc;
                        float x1a = acc[f][j][fr * 2];
                        float x1b = acc[f][j][fr * 2 + 1];
                        float x2a = xs[rl * 66 + d];
                        float x2b = xs[rl * 66 + d + 1];
                        float c0 = cosT[s * HD + d],     s0 = sinT[s * HD + d];
                        float c1 = cosT[s * HD + d + 1], s1 = sinT[s * HD + d + 1];
                        float y1a = (x1a * c0 - x2a * s0) * scale;
                        float y2a = (x2a * c0 + x1a * s0) * scale;
                        float y1b = (x1b * c1 - x2b * s1) * scale;
                        float y2b = (x2b * c1 + x1b * s1) * scale;
                        uint32_t h, l;
                        split2(y1a, y1b, h, l);
                        *(uint32_t*)&Ohi[(size_t)row * Ng + n0 + d] = h;
                        *(uint32_t*)&Olo[(size_t)row * Ng + n0 + d] = l;
                        split2(y2a, y2b, h, l);
                        *(uint32_t*)&Ohi[(size_t)row * Ng + n0 + 64 + d] = h;
                        *(uint32_t*)&Olo[(size_t)row * Ng + n0 + 64 + d] = l;
                    }
                }
            }
        }
    }
}

#define QSCALE (0.08838834764831845f * 1.4426950408889634f)

// Fused QKV projection + RoPE + split: bx 0..31 Q, 32..39 K, 40..47 V
__global__ __launch_bounds__(256, 2) void gemm_qkv(
    const __nv_bfloat16* __restrict__ dh, const __nv_bfloat16* __restrict__ dl,
    const __nv_bfloat16* __restrict__ wqh, const __nv_bfloat16* __restrict__ wql,
    const __nv_bfloat16* __restrict__ wkh, const __nv_bfloat16* __restrict__ wkl,
    const __nv_bfloat16* __restrict__ wvh, const __nv_bfloat16* __restrict__ wvl,
    __nv_bfloat16* __restrict__ qsh, __nv_bfloat16* __restrict__ qsl,
    __nv_bfloat16* __restrict__ ksh, __nv_bfloat16* __restrict__ ksl,
    __nv_bfloat16* __restrict__ vsh, __nv_bfloat16* __restrict__ vsl,
    const float* __restrict__ cosT, const float* __restrict__ sinT)
{
    extern __shared__ char dsm[];
    const int bx = blockIdx.x;
    const int m0 = blockIdx.y * 128;
    if (bx < 32) {
        gemm_core<1>(dh, dl, wqh, wql, nullptr, qsh, qsl, cosT, sinT, QSCALE,
                     NH * HD, m0, bx * 128, dsm);
    } else if (bx < 40) {
        gemm_core<1>(dh, dl, wkh, wkl, nullptr, ksh, ksl, cosT, sinT, 1.0f,
                     NKV * HD, m0, (bx - 32) * 128, dsm);
    } else {
        gemm_core<2>(dh, dl, wvh, wvl, nullptr, vsh, vsl, nullptr, nullptr, 1.0f,
                     NKV * HD, m0, (bx - 40) * 128, dsm);
    }
}

// O projection (plain fp32 epilogue)
__global__ __launch_bounds__(256, 2) void gemm_mm(
    const __nv_bfloat16* __restrict__ Ahi, const __nv_bfloat16* __restrict__ Alo,
    const __nv_bfloat16* __restrict__ Bhi, const __nv_bfloat16* __restrict__ Blo,
    float* __restrict__ C, int Ng)
{
    extern __shared__ char dsm[];
    gemm_core<0>(Ahi, Alo, Bhi, Blo, C, nullptr, nullptr, nullptr, nullptr, 1.0f,
                 Ng, blockIdx.y * 128, blockIdx.x * 128, dsm);
}

// ---------------------------------------------------------------------------
// One fused split kernel for all 5 fp32 inputs (sizes in float4 units)
// ---------------------------------------------------------------------------
#define SPLIT_N_DATA  4194304
#define SPLIT_N_WQ    4194304
#define SPLIT_N_WK    1048576
#define SPLIT_N_WV    1048576
#define SPLIT_N_WO    4194304
#define SPLIT_TOTAL   (SPLIT_N_DATA + SPLIT_N_WQ + SPLIT_N_WK + SPLIT_N_WV + SPLIT_N_WO)

__global__ void split_all(
    const float* __restrict__ data, const float* __restrict__ Wq,
    const float* __restrict__ Wk, const float* __restrict__ Wv,
    const float* __restrict__ Wo,
    __nv_bfloat16* __restrict__ dh, __nv_bfloat16* __restrict__ dl,
    __nv_bfloat16* __restrict__ qh, __nv_bfloat16* __restrict__ ql,
    __nv_bfloat16* __restrict__ kh, __nv_bfloat16* __restrict__ kl,
    __nv_bfloat16* __restrict__ vh, __nv_bfloat16* __restrict__ vl,
    __nv_bfloat16* __restrict__ oh, __nv_bfloat16* __restrict__ ol)
{
    int i = blockIdx.x * 256 + threadIdx.x;
    if (i >= SPLIT_TOTAL) return;
    const float* src; __nv_bfloat16 *hi, *lo; int off;
    if (i < SPLIT_N_DATA) { src = data; hi = dh; lo = dl; off = 0; }
    else if (i < SPLIT_N_DATA + SPLIT_N_WQ)
        { src = Wq; hi = qh; lo = ql; off = SPLIT_N_DATA; }
    else if (i < SPLIT_N_DATA + SPLIT_N_WQ + SPLIT_N_WK)
        { src = Wk; hi = kh; lo = kl; off = SPLIT_N_DATA + SPLIT_N_WQ; }
    else if (i < SPLIT_N_DATA + SPLIT_N_WQ + SPLIT_N_WK + SPLIT_N_WV)
        { src = Wv; hi = vh; lo = vl; off = SPLIT_N_DATA + SPLIT_N_WQ + SPLIT_N_WK; }
    else
        { src = Wo; hi = oh; lo = ol; off = SPLIT_N_DATA + SPLIT_N_WQ + SPLIT_N_WK + SPLIT_N_WV; }
    int j = i - off;
    float4 val = ((const float4*)src)[j];
    uint32_t h01, l01, h23, l23;
    split2(val.x, val.y, h01, l01);
    split2(val.z, val.w, h23, l23);
    ((uint32_t*)hi)[j * 2]     = h01;
    ((uint32_t*)hi)[j * 2 + 1] = h23;
    ((uint32_t*)lo)[j * 2]     = l01;
    ((uint32_t*)lo)[j * 2 + 1] = l23;
}

// ---------------------------------------------------------------------------
// Flash attention on HMMA (unchanged from round 9).
// ---------------------------------------------------------------------------
#define LDV 136
#define LDVB (LDV * 2)
#define FBUF (64 * LDVB)
#define FSTG (4 * FBUF)
#define FLASH2_SMEM (2 * FSTG)

__device__ __forceinline__ void load_kv(uint32_t sb, int tid,
    const __nv_bfloat16* __restrict__ khi, const __nv_bfloat16* __restrict__ klo,
    const __nv_bfloat16* __restrict__ vhi, const __nv_bfloat16* __restrict__ vlo,
    size_t kvbase)
{
#pragma unroll
    for (int i = 0; i < 4; i++) {
        int idx = tid + i * 256;
        int r = idx >> 4, sg = idx & 15;
        size_t g = kvbase + (size_t)r * (NKV * HD) + sg * 8;
        uint32_t s = sb + r * LDVB + sg * 16;
        cp16(s,            khi + g);
        cp16(s + FBUF,     klo + g);
        cp16(s + 2 * FBUF, vhi + g);
        cp16(s + 3 * FBUF, vlo + g);
    }
    asm volatile("cp.async.commit_group;" ::: "memory");
}

__global__ __launch_bounds__(256) void flash_mma(
    const __nv_bfloat16* __restrict__ qhi, const __nv_bfloat16* __restrict__ qlo,
    const __nv_bfloat16* __restrict__ khi, const __nv_bfloat16* __restrict__ klo,
    const __nv_bfloat16* __restrict__ vhi, const __nv_bfloat16* __restrict__ vlo,
    __nv_bfloat16* __restrict__ ohi, __nv_bfloat16* __restrict__ olo)
{
    extern __shared__ char dsm[];
    const uint32_t base = smem_u32(dsm);
    const int tid = threadIdx.x;
    const int lane = tid & 31;
    const int w = tid >> 5;
    const int qb = gridDim.x - 1 - blockIdx.x;   // heavy tiles first
    const int bh = blockIdx.y;
    const int b = bh / NH, h = bh % NH;
    const int kh = h / (NH / NKV);
    const int q0 = qb * 128;

    const size_t qbase = ((size_t)b * SEQ + q0) * (NH * HD) + (size_t)h * HD;
    const size_t kvh   = ((size_t)b * SEQ) * (NKV * HD) + (size_t)kh * HD;

    // Stage Q through stage-0 smem, extract frags to regs
#pragma unroll
    for (int i = 0; i < 8; i++) {
        int idx = tid + i * 256;
        int r = idx >> 4, sg = idx & 15;
        size_t g = qbase + (size_t)r * (NH * HD) + sg * 8;
        cp16(base + r * LDVB + sg * 16,            qhi + g);
        cp16(base + 2 * FBUF + r * LDVB + sg * 16, qlo + g);
    }
    asm volatile("cp.async.commit_group;" ::: "memory");
    asm volatile("cp.async.wait_group 0;" ::: "memory");
    __syncthreads();

    uint32_t qa_h[8][4], qa_l[8][4];
    {
        const uint32_t qrow = base + (w * 16 + (lane & 15)) * LDVB + (lane >> 4) * 16;
#pragma unroll
        for (int ks = 0; ks < 8; ks++) {
            ldm_x4(qa_h[ks], qrow + ks * 32);
            ldm_x4(qa_l[ks], qrow + 2 * FBUF + ks * 32);
        }
    }
    __syncthreads();

    float o[16][4];
#pragma unroll
    for (int j = 0; j < 16; j++)
#pragma unroll
        for (int q = 0; q < 4; q++) o[j][q] = 0.f;
    float m0 = -CUDART_INF_F, m1 = -CUDART_INF_F, l0 = 0.f, l1 = 0.f;

    const int n = 2 * (qb + 1);
    load_kv(base, tid, khi, klo, vhi, vlo, kvh);

    const uint32_t koff = ((lane & 7) + ((lane >> 4) << 3)) * LDVB + ((lane >> 3) & 1) * 16;
    const uint32_t voff = (lane & 15) * LDVB + (lane >> 4) * 16;

    for (int t = 0; t < n; t++) {
        asm volatile("cp.async.wait_group 0;" ::: "memory");
        __syncthreads();
        if (t + 1 < n)
            load_kv(base + ((t + 1) & 1) * FSTG, tid, khi, klo, vhi, vlo,
                    kvh + (size_t)(t + 1) * 64 * (NKV * HD));

        const uint32_t sb = base + (t & 1) * FSTG;
        const uint32_t vbh = sb + 2 * FBUF + voff;

        // S = Q K^T  (ks-outer: 8 independent accumulators per step)
        float s[8][4];
#pragma unroll
        for (int f = 0; f < 8; f++)
#pragma unroll
            for (int q = 0; q < 4; q++) s[f][q] = 0.f;

#pragma unroll
        for (int ks = 0; ks < 8; ks++) {
#pragma unroll
            for (int g = 0; g < 4; g++) {
                uint32_t kbh[4], kbl[4];
                ldm_x4(kbh, sb + g * 16 * LDVB + ks * 32 + koff);
                ldm_x4(kbl, sb + FBUF + g * 16 * LDVB + ks * 32 + koff);
                mma16816(s[2 * g],     qa_h[ks], kbh[0], kbh[1]);
                mma16816(s[2 * g + 1], qa_h[ks], kbh[2], kbh[3]);
                mma16816(s[2 * g],     qa_h[ks], kbl[0], kbl[1]);
                mma16816(s[2 * g + 1], qa_h[ks], kbl[2], kbl[3]);
                mma16816(s[2 * g],     qa_l[ks], kbh[0], kbh[1]);
                mma16816(s[2 * g + 1], qa_l[ks], kbh[2], kbh[3]);
            }
        }

        // Causal mask (last two kv tiles)
        if (t >= n - 2) {
            const int rA = q0 + w * 16 + (lane >> 2);
            const int cb = t * 64 + 2 * (lane & 3);
#pragma unroll
            for (int f = 0; f < 8; f++) {
                int c = cb + f * 8;
                if (c > rA)         s[f][0] = -1e30f;
                if (c + 1 > rA)     s[f][1] = -1e30f;
                if (c > rA + 8)     s[f][2] = -1e30f;
                if (c + 1 > rA + 8) s[f][3] = -1e30f;
            }
        }

        // Single-phase online softmax over all 64 cols
        float mn0 = m0, mn1 = m1;
#pragma unroll
        for (int f = 0; f < 8; f++) {
            mn0 = fmaxf(mn0, fmaxf(s[f][0], s[f][1]));
            mn1 = fmaxf(mn1, fmaxf(s[f][2], s[f][3]));
        }
        mn0 = fmaxf(mn0, __shfl_xor_sync(0xffffffffu, mn0, 1));
        mn0 = fmaxf(mn0, __shfl_xor_sync(0xffffffffu, mn0, 2));
        mn1 = fmaxf(mn1, __shfl_xor_sync(0xffffffffu, mn1, 1));
        mn1 = fmaxf(mn1, __shfl_xor_sync(0xffffffffu, mn1, 2));
        const float cr0 = ex2(m0 - mn0), cr1 = ex2(m1 - mn1);
        m0 = mn0; m1 = mn1;
        l0 *= cr0; l1 *= cr1;
#pragma unroll
        for (int j = 0; j < 16; j++) {
            o[j][0] *= cr0; o[j][1] *= cr0;
            o[j][2] *= cr1; o[j][3] *= cr1;
        }

        float rs0 = 0.f, rs1 = 0.f;
        uint32_t ph01[8], ph23[8], pl01[8], pl23[8];
#pragma unroll
        for (int f = 0; f < 8; f++) {
            float p0 = ex2(s[f][0] - m0);
            float p1 = ex2(s[f][1] - m0);
            float p2 = ex2(s[f][2] - m1);
            float p3 = ex2(s[f][3] - m1);
            rs0 += p0 + p1;
            rs1 += p2 + p3;
            tsplit2(p0, p1, ph01[f], pl01[f]);
            tsplit2(p2, p3, ph23[f], pl23[f]);
        }
        l0 += rs0;
        l1 += rs1;

        // O += P V (3 terms), kc-outer / g-inner
#pragma unroll
        for (int kc = 0; kc < 4; kc++) {
            uint32_t ah[4] = {ph01[2 * kc], ph23[2 * kc],
                              ph01[2 * kc + 1], ph23[2 * kc + 1]};
            uint32_t al[4] = {pl01[2 * kc], pl23[2 * kc],
                              pl01[2 * kc + 1], pl23[2 * kc + 1]};
#pragma unroll
            for (int g = 0; g < 8; g++) {
                uint32_t vh4[4], vl4[4];
                ldm_x4t(vh4, vbh + kc * 16 * LDVB + g * 32);
                ldm_x4t(vl4, vbh + FBUF + kc * 16 * LDVB + g * 32);
                mma16816(o[2 * g],     ah, vh4[0], vh4[1]);
                mma16816(o[2 * g + 1], ah, vh4[2], vh4[3]);
                mma16816(o[2 * g],     ah, vl4[0], vl4[1]);
                mma16816(o[2 * g + 1], ah, vl4[2], vl4[3]);
                mma16816(o[2 * g],     al, vh4[0], vh4[1]);
                mma16816(o[2 * g + 1], al, vh4[2], vh4[3]);
            }
        }
    }

    // Deferred cross-lane l reduction
    l0 += __shfl_xor_sync(0xffffffffu, l0, 1);
    l0 += __shfl_xor_sync(0xffffffffu, l0, 2);
    l1 += __shfl_xor_sync(0xffffffffu, l1, 1);
    l1 += __shfl_xor_sync(0xffffffffu, l1, 2);

    const float il0 = 1.f / l0, il1 = 1.f / l1;
    const int rA = q0 + w * 16 + (lane >> 2);
    const size_t oA = ((size_t)b * SEQ + rA) * (NH * HD) + (size_t)h * HD + 2 * (lane & 3);
    const size_t oB = oA + (size_t)8 * (NH * HD);
#pragma unroll
    for (int j = 0; j < 16; j++) {
        uint32_t h01, lo01, h23, lo23;
        split2(o[j][0] * il0, o[j][1] * il0, h01, lo01);
        split2(o[j][2] * il1, o[j][3] * il1, h23, lo23);
        *(uint32_t*)&ohi[oA + j * 8] = h01;
        *(uint32_t*)&olo[oA + j * 8] = lo01;
        *(uint32_t*)&ohi[oB + j * 8] = h23;
        *(uint32_t*)&olo[oB + j * 8] = lo23;
    }
}

// ---------------------------------------------------------------------------
// Launcher
// ---------------------------------------------------------------------------
extern "C" void kernel_launch(void* const* d_in, const int* in_sizes, int n_in,
                              void* d_out, int out_size)
{
    const float* data = (const float*)d_in[0];
    const float* Wq   = (const float*)d_in[1];
    const float* Wk   = (const float*)d_in[2];
    const float* Wv   = (const float*)d_in[3];
    const float* Wo   = (const float*)d_in[4];
    const float* cosT = (const float*)d_in[5];
    const float* sinT = (const float*)d_in[6];
    float* out = (float*)d_out;
    (void)in_sizes; (void)n_in; (void)out_size;

    __nv_bfloat16 *dh, *dl, *wqh, *wql, *wkh, *wkl, *wvh, *wvl, *woh, *wol, *ah, *al;
    __nv_bfloat16 *qsh, *qsl, *ksh, *ksl, *vsh, *vsl;
    cudaGetSymbolAddress((void**)&dh,  g_data_hi);
    cudaGetSymbolAddress((void**)&dl,  g_data_lo);
    cudaGetSymbolAddress((void**)&wqh, g_wq_hi);
    cudaGetSymbolAddress((void**)&wql, g_wq_lo);
    cudaGetSymbolAddress((void**)&wkh, g_wk_hi);
    cudaGetSymbolAddress((void**)&wkl, g_wk_lo);
    cudaGetSymbolAddress((void**)&wvh, g_wv_hi);
    cudaGetSymbolAddress((void**)&wvl, g_wv_lo);
    cudaGetSymbolAddress((void**)&woh, g_wo_hi);
    cudaGetSymbolAddress((void**)&wol, g_wo_lo);
    cudaGetSymbolAddress((void**)&ah,  g_attn_hi);
    cudaGetSymbolAddress((void**)&al,  g_attn_lo);
    cudaGetSymbolAddress((void**)&qsh, g_qs_hi);
    cudaGetSymbolAddress((void**)&qsl, g_qs_lo);
    cudaGetSymbolAddress((void**)&ksh, g_ks_hi);
    cudaGetSymbolAddress((void**)&ksl, g_ks_lo);
    cudaGetSymbolAddress((void**)&vsh, g_vs_hi);
    cudaGetSymbolAddress((void**)&vsl, g_vs_lo);

    cudaFuncSetAttribute(gemm_qkv,
                         cudaFuncAttributeMaxDynamicSharedMemorySize, GEMM_SMEM);
    cudaFuncSetAttribute(gemm_mm,
                         cudaFuncAttributeMaxDynamicSharedMemorySize, GEMM_SMEM);
    cudaFuncSetAttribute(flash_mma,
                         cudaFuncAttributeMaxDynamicSharedMemorySize, FLASH2_SMEM);

    // 1: all input splits
    split_all<<<(SPLIT_TOTAL + 255) / 256, 256>>>(data, Wq, Wk, Wv, Wo,
                                          dh, dl, wqh, wql, wkh, wkl, wvh, wvl, woh, wol);

    // 2: fused QKV projection + RoPE + split (48 column tiles)
    gemm_qkv<<<dim3(48, TOKENS / 128), 256, GEMM_SMEM>>>(
        dh, dl, wqh, wql, wkh, wkl, wvh, wvl,
        qsh, qsl, ksh, ksl, vsh, vsl, cosT, sinT);

    // 3: flash attention (writes bf16 hi/lo)
    flash_mma<<<dim3(SEQ / 128, BATCH * NH), 256, FLASH2_SMEM>>>(
        qsh, qsl, ksh, ksl, vsh, vsl, ah, al);

    // 4: output projection
    gemm_mm<<<dim3(DIM / 128, TOKENS / 128), 256, GEMM_SMEM>>>(ah, al, woh, wol, out, DIM);
}